// round 1
// baseline (speedup 1.0000x reference)
#include <cuda_runtime.h>
#include <math.h>

// Problem constants (capacities for static scratch; runtime dims derived from in_sizes)
#define DLC 128
static const int N_MAX = 50000;
static const int E_MAX = 800000;

// ---------------- static device scratch (no allocations allowed) ----------------
__device__ float g_h   [(size_t)N_MAX * DLC];
__device__ float g_bufA[(size_t)N_MAX * 256];
__device__ float g_bufB[(size_t)N_MAX * 256];
__device__ int   g_counts[N_MAX];
__device__ int   g_rowptr[N_MAX + 1];
__device__ int   g_cursor[N_MAX];
__device__ int   g_csrc  [E_MAX];
__device__ float g_dinv  [N_MAX];

// ---------------- small kernels ----------------

__global__ void count_deg_k(const int* __restrict__ dst, int E, int* __restrict__ counts) {
    int e = blockIdx.x * blockDim.x + threadIdx.x;
    if (e < E) atomicAdd(&counts[dst[e]], 1);
}

// single-block exclusive scan over counts -> rowptr, cursor
__global__ void scan_k(const int* __restrict__ counts, int* __restrict__ rowptr,
                       int* __restrict__ cursor, int n) {
    __shared__ int sm[1024];
    int tid = threadIdx.x;
    int chunk = (n + 1023) >> 10;
    int s = tid * chunk;
    int e = min(s + chunk, n);
    int sum = 0;
    for (int i = s; i < e && i < n; i++) sum += counts[i];
    sm[tid] = sum;
    __syncthreads();
    for (int off = 1; off < 1024; off <<= 1) {
        int v = (tid >= off) ? sm[tid - off] : 0;
        __syncthreads();
        sm[tid] += v;
        __syncthreads();
    }
    int run = (tid > 0) ? sm[tid - 1] : 0;
    for (int i = s; i < e && i < n; i++) {
        rowptr[i] = run;
        cursor[i] = run;
        run += counts[i];
    }
    if (e >= n) rowptr[n] = run;  // tail threads all write total (same value)
}

__global__ void dinv_k(const int* __restrict__ counts, float* __restrict__ dinv, int n) {
    int i = blockIdx.x * blockDim.x + threadIdx.x;
    if (i < n) dinv[i] = rsqrtf((float)counts[i] + 1.0f);
}

__global__ void fill_csr_k(const int* __restrict__ src, const int* __restrict__ dst, int E,
                           int* __restrict__ cursor, int* __restrict__ csrc) {
    int e = blockIdx.x * blockDim.x + threadIdx.x;
    if (e < E) {
        int d = dst[e];
        int p = atomicAdd(&cursor[d], 1);
        csrc[p] = src[e];
    }
}

// out[n][j] = sum_{e in in-edges(n)} g[src][j]*dinv[src]*dinv[n] + g[n][j]*dinv[n]^2 + bias[j]
__global__ void agg_k(const float* __restrict__ gmat, float* __restrict__ out,
                      const int* __restrict__ rowptr, const int* __restrict__ csrc,
                      const float* __restrict__ dinv, const float* __restrict__ bias, int n) {
    int node = blockIdx.x;
    int j = threadIdx.x;
    float dn = dinv[node];
    float acc = gmat[(size_t)node * DLC + j] * dn * dn + bias[j];
    int beg = rowptr[node];
    int end = rowptr[node + 1];
    for (int e = beg; e < end; e++) {
        int s = csrc[e];
        acc += gmat[(size_t)s * DLC + j] * (dinv[s] * dn);
    }
    out[(size_t)node * DLC + j] = acc;
}

__global__ void reparam_k(const float* __restrict__ mu, const float* __restrict__ sd,
                          const float* __restrict__ eps, float* __restrict__ h, int n) {
    int i = blockIdx.x * blockDim.x + threadIdx.x;
    if (i < n) h[i] = fmaf(sd[i], eps[i], mu[i]);
}

// one block per graph; batch_ids sorted -> binary search range, no atomics to gmem
__global__ void pool_k(const float* __restrict__ yp, const int* __restrict__ bids,
                       float* __restrict__ out, int N, int dout) {
    int g = blockIdx.x;
    // lower_bound(g)
    int lo = 0, hi = N;
    while (lo < hi) { int m = (lo + hi) >> 1; if (bids[m] < g) lo = m + 1; else hi = m; }
    int start = lo;
    lo = start; hi = N;
    while (lo < hi) { int m = (lo + hi) >> 1; if (bids[m] < g + 1) lo = m + 1; else hi = m; }
    int end = lo;

    __shared__ float sm[16];
    if (threadIdx.x < dout) sm[threadIdx.x] = 0.0f;
    __syncthreads();
    float loc[10];
#pragma unroll
    for (int f = 0; f < 10; f++) loc[f] = 0.0f;
    for (int nidx = start + threadIdx.x; nidx < end; nidx += blockDim.x) {
#pragma unroll
        for (int f = 0; f < 10; f++) loc[f] += yp[(size_t)nidx * dout + f];
    }
#pragma unroll
    for (int f = 0; f < 10; f++) atomicAdd(&sm[f], loc[f]);
    __syncthreads();
    int cnt = end - start;
    float inv = 1.0f / (float)max(cnt, 1);
    if (threadIdx.x < dout) out[(size_t)g * dout + threadIdx.x] = sm[threadIdx.x] * inv;
}

// ---------------- SGEMM: C = act(A[M,K] @ W[K,Nout] + bias) ----------------
// BM=128, BN=128, BK=16, 256 threads, 8x8 per thread register tile.
// ACT: 0=none, 1=sigmoid, 2=relu, 3=softplus(z-5)

__device__ __forceinline__ float apply_act(float z, int ACT) {
    if (ACT == 1) return 1.0f / (1.0f + expf(-z));
    if (ACT == 2) return fmaxf(z, 0.0f);
    if (ACT == 3) {
        float t = z - 5.0f;
        return fmaxf(t, 0.0f) + log1pf(expf(-fabsf(t)));
    }
    return z;
}

template <int ACT>
__global__ __launch_bounds__(256, 2)
void sgemm_k(const float* __restrict__ A, const float* __restrict__ W,
             const float* __restrict__ bias, float* __restrict__ C,
             int M, int K, int Nout) {
    __shared__ float As[16][132];
    __shared__ float Ws[16][136];
    const int tid = threadIdx.x;
    const int tx = tid & 15;
    const int ty = tid >> 4;
    const int rowBase = blockIdx.x * 128;
    const int colBase = blockIdx.y * 128;

    float acc[8][8];
#pragma unroll
    for (int i = 0; i < 8; i++)
#pragma unroll
        for (int j = 0; j < 8; j++) acc[i][j] = 0.0f;

    const int aC = (tid & 3) * 4;  // k-col within tile (float4)
    const int aR = tid >> 2;       // 0..63
    const int wR = tid >> 4;       // 0..15
    const int wC = (tid & 15) * 8; // 0..120

    for (int kt = 0; kt < K; kt += 16) {
#pragma unroll
        for (int it = 0; it < 2; it++) {
            int r = aR + it * 64;
            int gr = rowBase + r;
            float4 v = make_float4(0.f, 0.f, 0.f, 0.f);
            if (gr < M) v = *reinterpret_cast<const float4*>(A + (size_t)gr * K + kt + aC);
            As[aC + 0][r] = v.x;
            As[aC + 1][r] = v.y;
            As[aC + 2][r] = v.z;
            As[aC + 3][r] = v.w;
        }
        {
            int gr = kt + wR;
#pragma unroll
            for (int u = 0; u < 8; u++) {
                int gc = colBase + wC + u;
                Ws[wR][wC + u] = (gc < Nout) ? __ldg(W + (size_t)gr * Nout + gc) : 0.0f;
            }
        }
        __syncthreads();
#pragma unroll
        for (int kk = 0; kk < 16; kk++) {
            float a[8], b[8];
#pragma unroll
            for (int i = 0; i < 8; i++) a[i] = As[kk][ty * 8 + i];
#pragma unroll
            for (int j = 0; j < 8; j++) b[j] = Ws[kk][tx * 8 + j];
#pragma unroll
            for (int i = 0; i < 8; i++)
#pragma unroll
                for (int j = 0; j < 8; j++) acc[i][j] = fmaf(a[i], b[j], acc[i][j]);
        }
        __syncthreads();
    }

#pragma unroll
    for (int i = 0; i < 8; i++) {
        int gr = rowBase + ty * 8 + i;
        if (gr >= M) continue;
#pragma unroll
        for (int j = 0; j < 8; j++) {
            int gc = colBase + tx * 8 + j;
            if (gc >= Nout) continue;
            float z = acc[i][j] + (bias ? __ldg(bias + gc) : 0.0f);
            C[(size_t)gr * Nout + gc] = apply_act(z, ACT);
        }
    }
}

// ---------------- launch ----------------

extern "C" void kernel_launch(void* const* d_in, const int* in_sizes, int n_in,
                              void* d_out, int out_size) {
    const float* x     = (const float*)d_in[0];
    const int*   ei    = (const int*)d_in[1];
    const int*   bids  = (const int*)d_in[2];
    const float* y     = (const float*)d_in[3];
    const float* eps   = (const float*)d_in[4];
    const float* W_in  = (const float*)d_in[5];
    const float* b_in  = (const float*)d_in[6];
    const float* W_gcn = (const float*)d_in[7];
    const float* b_gcn = (const float*)d_in[8];
    const float* W_enc = (const float*)d_in[9];
    const float* b_enc = (const float*)d_in[10];
    const float* W_mu  = (const float*)d_in[11];
    const float* b_mu  = (const float*)d_in[12];
    const float* W_std = (const float*)d_in[13];
    const float* b_std = (const float*)d_in[14];
    const float* Wd[5];
    const float* bd[5];
    for (int i = 0; i < 5; i++) {
        Wd[i] = (const float*)d_in[15 + 2 * i];
        bd[i] = (const float*)d_in[16 + 2 * i];
    }
    const float* Wo = (const float*)d_in[25];
    const float* bo = (const float*)d_in[26];

    const int dl   = in_sizes[6];             // 128
    const int din  = in_sizes[5] / dl;        // 32
    const int N    = in_sizes[0] / din;       // 50000
    const int E    = in_sizes[1] / 2;         // 800000
    const int dout = in_sizes[26];            // 10
    const int G    = in_sizes[3] / dout;      // 256
    const int Khops = in_sizes[4] / (N * dl); // 3

    float *h, *bufA, *bufB, *dinv;
    int *counts, *rowptr, *cursor, *csrc;
    cudaGetSymbolAddress((void**)&h, g_h);
    cudaGetSymbolAddress((void**)&bufA, g_bufA);
    cudaGetSymbolAddress((void**)&bufB, g_bufB);
    cudaGetSymbolAddress((void**)&dinv, g_dinv);
    cudaGetSymbolAddress((void**)&counts, g_counts);
    cudaGetSymbolAddress((void**)&rowptr, g_rowptr);
    cudaGetSymbolAddress((void**)&cursor, g_cursor);
    cudaGetSymbolAddress((void**)&csrc, g_csrc);

    float* out     = (float*)d_out;
    float* out_mu  = out + (size_t)G * dout;
    float* out_std = out_mu + (size_t)N * dl;
    float* out_y   = out_std + (size_t)N * dl;

    const int* src = ei;
    const int* dst = ei + E;

    // --- CSR + normalization ---
    cudaMemsetAsync(counts, 0, (size_t)N * sizeof(int));
    count_deg_k<<<(E + 255) / 256, 256>>>(dst, E, counts);
    scan_k<<<1, 1024>>>(counts, rowptr, cursor, N);
    dinv_k<<<(N + 255) / 256, 256>>>(counts, dinv, N);
    fill_csr_k<<<(E + 255) / 256, 256>>>(src, dst, E, cursor, csrc);

    dim3 g128((N + 127) / 128, 1);

    // --- input layer: h = sigmoid(x @ W_in + b_in) ---
    sgemm_k<1><<<g128, 256>>>(x, W_in, b_in, h, N, din, dl);

    // --- K hops ---
    for (int i = 0; i < Khops; i++) {
        sgemm_k<0><<<g128, 256>>>(h, W_gcn, (const float*)nullptr, bufA, N, dl, dl);
        agg_k<<<N, 128>>>(bufA, bufB, rowptr, csrc, dinv, b_gcn, N);
        const float* cur = bufB;
        float* nxt = bufA;
        for (int j = 0; j < 5; j++) {
            sgemm_k<1><<<g128, 256>>>(cur, W_enc + (size_t)j * dl * dl, b_enc + (size_t)j * dl,
                                      nxt, N, dl, dl);
            const float* tmp = cur;
            cur = nxt;
            nxt = (float*)tmp;
        }
        sgemm_k<0><<<g128, 256>>>(cur, W_mu, b_mu, out_mu, N, dl, dl);
        sgemm_k<3><<<g128, 256>>>(cur, W_std, b_std, out_std, N, dl, dl);
        reparam_k<<<((size_t)N * dl + 255) / 256, 256>>>(out_mu, out_std,
                                                         eps + (size_t)i * N * dl, h,
                                                         N * dl);
    }

    // --- decoder MLP ---
    int dims[6] = {dl, in_sizes[16], in_sizes[18], in_sizes[20], in_sizes[22], in_sizes[24]};
    const float* cur = h;
    float* bufs[2] = {bufA, bufB};
    int pb = 0;
    for (int l = 0; l < 5; l++) {
        dim3 gd((N + 127) / 128, (dims[l + 1] + 127) / 128);
        sgemm_k<2><<<gd, 256>>>(cur, Wd[l], bd[l], bufs[pb], N, dims[l], dims[l + 1]);
        cur = bufs[pb];
        pb ^= 1;
    }
    // yp = sigmoid(d @ Wo + bo)  [N, dout]
    sgemm_k<1><<<g128, 256>>>(cur, Wo, bo, bufs[pb], N, dims[5], dout);

    // --- pooling + y passthrough ---
    pool_k<<<G, 256>>>(bufs[pb], bids, out, N, dout);
    cudaMemcpyAsync(out_y, y, (size_t)G * dout * sizeof(float), cudaMemcpyDeviceToDevice);
}

// round 10
// speedup vs baseline: 1.4252x; 1.4252x over previous
#include <cuda_runtime.h>
#include <cstdint>
#include <math.h>
#include <mma.h>

using namespace nvcuda;

#define DLC 128
#define TBS 256
static const int N_MAX = 50000;
static const int E_MAX = 800000;

// ---------------- static device scratch ----------------
__device__ float g_h   [(size_t)N_MAX * DLC];
__device__ float g_bufA[(size_t)N_MAX * 256];
__device__ float g_bufB[(size_t)N_MAX * 256];
__device__ int   g_counts[N_MAX];
__device__ int   g_rowptr[N_MAX + 1];
__device__ int   g_cursor[N_MAX];
__device__ int   g_csrc  [E_MAX];
__device__ float g_dinv  [N_MAX];

// ---------------- WMMA tf32 GEMM ----------------
// C[M,Ntrue] = act(A[M,K] @ W[K,Nout] + bias), W row-major [K, Nout] (no transpose needed).
// Block tile 128x128, 8 warps in 4x2, warp tile 32x64 of 16x16x8 tf32 fragments.
#define BM 128
#define BN 128
#define BK 32
#define LDA 36
#define LDB 132
#define LDCS 132
// dynamic smem layout (floats): As[128*36] | Ws[32*132] | Cs[128*132]
#define OFF_AS 0
#define OFF_WS (128 * LDA)
#define OFF_CS (OFF_WS + BK * LDB)
#define SMEM_FLOATS (OFF_CS + 128 * LDCS)
#define SMEM_BYTES (SMEM_FLOATS * 4)

__device__ __forceinline__ float apply_act(float z, int ACT) {
    if (ACT == 1) return 1.0f / (1.0f + __expf(-z));
    if (ACT == 2) return fmaxf(z, 0.0f);
    if (ACT == 3) {
        float t = z - 5.0f;
        return fmaxf(t, 0.0f) + log1pf(__expf(-fabsf(t)));
    }
    return z;
}

template <int ACT>
__global__ __launch_bounds__(TBS, 2)
void wgemm_k(const float* __restrict__ A, const float* __restrict__ W,
             const float* __restrict__ bias, float* __restrict__ C,
             int M, int K, int Nout, int Ntrue, int ldC) {
    extern __shared__ float sm[];
    float* As = sm + OFF_AS;
    float* Ws = sm + OFF_WS;
    float* Cs = sm + OFF_CS;

    const int tid = threadIdx.x;
    const int wid = tid >> 5;
    const int mBase = blockIdx.x * BM;
    const int colBase = blockIdx.y * BN;
    const int warpRow = wid & 3;   // 0..3 -> 32 rows each
    const int warpCol = wid >> 2;  // 0..1 -> 64 cols each

    wmma::fragment<wmma::accumulator, 16, 16, 8, float> acc[2][4];
#pragma unroll
    for (int i = 0; i < 2; i++)
#pragma unroll
        for (int j = 0; j < 4; j++) wmma::fill_fragment(acc[i][j], 0.0f);

    // loader indices
    const int ar = tid >> 1;               // A row within tile (2 thr/row)
    const int ac0 = (tid & 1) * 16;        // A col start (16 floats per thr)
    const int wr = tid >> 3;               // W k-row within chunk (8 thr/row)
    const int wc0 = (tid & 7) * 16;        // W col start (16 floats per thr)

    const bool wVec = ((Nout & 3) == 0);   // float4 loads of W only if row stride is 16B-aligned

    const int nch = (K + BK - 1) / BK;
    for (int ch = 0; ch < nch; ch++) {
        const int k0 = ch * BK;
        // --- A tile: [128][32], zero-pad out-of-range rows/cols, tf32-round ---
        {
            const int gr = mBase + ar;
            const bool rok = (gr < M);
            const float* Arow = A + (size_t)gr * K + k0;
#pragma unroll
            for (int i = 0; i < 4; i++) {
                int c = ac0 + i * 4;
                float4 v = make_float4(0.f, 0.f, 0.f, 0.f);
                if (rok && (k0 + c + 3 < K)) v = *(const float4*)(Arow + c);
                float* d = As + ar * LDA + c;
                d[0] = wmma::__float_to_tf32(v.x);
                d[1] = wmma::__float_to_tf32(v.y);
                d[2] = wmma::__float_to_tf32(v.z);
                d[3] = wmma::__float_to_tf32(v.w);
            }
        }
        // --- W tile: [32][128], zero-pad, tf32-round ---
        {
            const int kr = k0 + wr;
            const bool kok = (kr < K);
            const float* Wrow = W + (size_t)kr * Nout + colBase;
#pragma unroll
            for (int i = 0; i < 4; i++) {
                int c = wc0 + i * 4;
                int gc = colBase + c;
                float* d = Ws + wr * LDB + c;
                if (kok && wVec && (gc + 3 < Nout)) {
                    float4 v = *(const float4*)(Wrow + c);
                    d[0] = wmma::__float_to_tf32(v.x);
                    d[1] = wmma::__float_to_tf32(v.y);
                    d[2] = wmma::__float_to_tf32(v.z);
                    d[3] = wmma::__float_to_tf32(v.w);
                } else {
#pragma unroll
                    for (int u = 0; u < 4; u++) {
                        float v = (kok && (gc + u < Nout)) ? Wrow[c + u] : 0.0f;
                        d[u] = wmma::__float_to_tf32(v);
                    }
                }
            }
        }
        __syncthreads();

#pragma unroll
        for (int kk = 0; kk < BK / 8; kk++) {
            wmma::fragment<wmma::matrix_a, 16, 16, 8, wmma::precision::tf32, wmma::row_major> af[2];
            wmma::fragment<wmma::matrix_b, 16, 16, 8, wmma::precision::tf32, wmma::row_major> bf[4];
#pragma unroll
            for (int i = 0; i < 2; i++)
                wmma::load_matrix_sync(af[i], As + (warpRow * 32 + i * 16) * LDA + kk * 8, LDA);
#pragma unroll
            for (int j = 0; j < 4; j++)
                wmma::load_matrix_sync(bf[j], Ws + (kk * 8) * LDB + warpCol * 64 + j * 16, LDB);
#pragma unroll
            for (int i = 0; i < 2; i++)
#pragma unroll
                for (int j = 0; j < 4; j++)
                    wmma::mma_sync(acc[i][j], af[i], bf[j], acc[i][j]);
        }
        __syncthreads();
    }

    // --- epilogue: fragments -> SMEM -> activation -> gmem ---
#pragma unroll
    for (int i = 0; i < 2; i++)
#pragma unroll
        for (int j = 0; j < 4; j++)
            wmma::store_matrix_sync(Cs + (warpRow * 32 + i * 16) * LDCS + warpCol * 64 + j * 16,
                                    acc[i][j], LDCS, wmma::mem_row_major);
    __syncthreads();

    {
        const int r = tid >> 1;
        const int ch = (tid & 1) * 64;
        const int gr = mBase + r;
        if (gr < M) {
            const int colRem = Ntrue - colBase - ch;  // may be <= 0
            float* Crow = C + (size_t)gr * ldC + colBase + ch;
            const float* Srow = Cs + r * LDCS + ch;
            if (colRem >= 64 && ((ldC & 3) == 0)) {
#pragma unroll
                for (int c = 0; c < 64; c += 4) {
                    float4 v;
                    v.x = apply_act(Srow[c + 0] + (bias ? __ldg(bias + colBase + ch + c + 0) : 0.f), ACT);
                    v.y = apply_act(Srow[c + 1] + (bias ? __ldg(bias + colBase + ch + c + 1) : 0.f), ACT);
                    v.z = apply_act(Srow[c + 2] + (bias ? __ldg(bias + colBase + ch + c + 2) : 0.f), ACT);
                    v.w = apply_act(Srow[c + 3] + (bias ? __ldg(bias + colBase + ch + c + 3) : 0.f), ACT);
                    *(float4*)(Crow + c) = v;
                }
            } else {
                for (int c = 0; c < 64 && c < colRem; c++) {
                    float z = Srow[c] + (bias ? __ldg(bias + colBase + ch + c) : 0.f);
                    Crow[c] = apply_act(z, ACT);
                }
            }
        }
    }
}

// ---------------- graph/CSR kernels ----------------
__global__ void count_deg_k(const int* __restrict__ dst, int E, int* __restrict__ counts) {
    int e = blockIdx.x * blockDim.x + threadIdx.x;
    if (e < E) atomicAdd(&counts[dst[e]], 1);
}

__global__ void scan_k(const int* __restrict__ counts, int* __restrict__ rowptr,
                       int* __restrict__ cursor, int n) {
    __shared__ int sm[1024];
    int tid = threadIdx.x;
    int chunk = (n + 1023) >> 10;
    int s = tid * chunk;
    int e = min(s + chunk, n);
    int sum = 0;
    for (int i = s; i < e && i < n; i++) sum += counts[i];
    sm[tid] = sum;
    __syncthreads();
    for (int off = 1; off < 1024; off <<= 1) {
        int v = (tid >= off) ? sm[tid - off] : 0;
        __syncthreads();
        sm[tid] += v;
        __syncthreads();
    }
    int run = (tid > 0) ? sm[tid - 1] : 0;
    for (int i = s; i < e && i < n; i++) {
        rowptr[i] = run;
        cursor[i] = run;
        run += counts[i];
    }
    if (e >= n) rowptr[n] = run;
}

__global__ void dinv_k(const int* __restrict__ counts, float* __restrict__ dinv, int n) {
    int i = blockIdx.x * blockDim.x + threadIdx.x;
    if (i < n) dinv[i] = rsqrtf((float)counts[i] + 1.0f);
}

__global__ void fill_csr_k(const int* __restrict__ src, const int* __restrict__ dst, int E,
                           int* __restrict__ cursor, int* __restrict__ csrc) {
    int e = blockIdx.x * blockDim.x + threadIdx.x;
    if (e < E) {
        int d = dst[e];
        int p = atomicAdd(&cursor[d], 1);
        csrc[p] = src[e];
    }
}

__global__ void agg_k(const float* __restrict__ gmat, float* __restrict__ out,
                      const int* __restrict__ rowptr, const int* __restrict__ csrc,
                      const float* __restrict__ dinv, const float* __restrict__ bias, int n) {
    int node = blockIdx.x;
    int j = threadIdx.x;
    float dn = dinv[node];
    float acc = gmat[(size_t)node * DLC + j] * dn * dn + bias[j];
    int beg = rowptr[node];
    int end = rowptr[node + 1];
    for (int e = beg; e < end; e++) {
        int s = csrc[e];
        acc += gmat[(size_t)s * DLC + j] * (dinv[s] * dn);
    }
    out[(size_t)node * DLC + j] = acc;
}

__global__ void reparam_k(const float* __restrict__ mu, const float* __restrict__ sd,
                          const float* __restrict__ eps, float* __restrict__ h, int n) {
    int i = blockIdx.x * blockDim.x + threadIdx.x;
    if (i < n) h[i] = fmaf(sd[i], eps[i], mu[i]);
}

__global__ void pool_k(const float* __restrict__ yp, const int* __restrict__ bids,
                       float* __restrict__ out, int N, int dout) {
    int g = blockIdx.x;
    int lo = 0, hi = N;
    while (lo < hi) { int m = (lo + hi) >> 1; if (bids[m] < g) lo = m + 1; else hi = m; }
    int start = lo;
    lo = start; hi = N;
    while (lo < hi) { int m = (lo + hi) >> 1; if (bids[m] < g + 1) lo = m + 1; else hi = m; }
    int end = lo;

    __shared__ float sm[16];
    if (threadIdx.x < dout) sm[threadIdx.x] = 0.0f;
    __syncthreads();
    float loc[10];
#pragma unroll
    for (int f = 0; f < 10; f++) loc[f] = 0.0f;
    for (int nidx = start + threadIdx.x; nidx < end; nidx += blockDim.x) {
#pragma unroll
        for (int f = 0; f < 10; f++) loc[f] += yp[(size_t)nidx * dout + f];
    }
#pragma unroll
    for (int f = 0; f < 10; f++) atomicAdd(&sm[f], loc[f]);
    __syncthreads();
    int cnt = end - start;
    float inv = 1.0f / (float)max(cnt, 1);
    if (threadIdx.x < dout) out[(size_t)g * dout + threadIdx.x] = sm[threadIdx.x] * inv;
}

// ---------------- launch ----------------
extern "C" void kernel_launch(void* const* d_in, const int* in_sizes, int n_in,
                              void* d_out, int out_size) {
    const float* x     = (const float*)d_in[0];
    const int*   ei    = (const int*)d_in[1];
    const int*   bids  = (const int*)d_in[2];
    const float* y     = (const float*)d_in[3];
    const float* eps   = (const float*)d_in[4];
    const float* W_in  = (const float*)d_in[5];
    const float* b_in  = (const float*)d_in[6];
    const float* W_gcn = (const float*)d_in[7];
    const float* b_gcn = (const float*)d_in[8];
    const float* W_enc = (const float*)d_in[9];
    const float* b_enc = (const float*)d_in[10];
    const float* W_mu  = (const float*)d_in[11];
    const float* b_mu  = (const float*)d_in[12];
    const float* W_std = (const float*)d_in[13];
    const float* b_std = (const float*)d_in[14];
    const float* Wd[5];
    const float* bd[5];
    for (int i = 0; i < 5; i++) {
        Wd[i] = (const float*)d_in[15 + 2 * i];
        bd[i] = (const float*)d_in[16 + 2 * i];
    }
    const float* Wo = (const float*)d_in[25];
    const float* bo = (const float*)d_in[26];

    const int dl    = in_sizes[6];             // 128
    const int din   = in_sizes[5] / dl;        // 32
    const int N     = in_sizes[0] / din;       // 50000
    const int E     = in_sizes[1] / 2;         // 800000
    const int dout  = in_sizes[26];            // 10
    const int G     = in_sizes[3] / dout;      // 256
    const int Khops = in_sizes[4] / (N * dl);  // 3

    float *h, *bufA, *bufB, *dinv;
    int *counts, *rowptr, *cursor, *csrc;
    cudaGetSymbolAddress((void**)&h, g_h);
    cudaGetSymbolAddress((void**)&bufA, g_bufA);
    cudaGetSymbolAddress((void**)&bufB, g_bufB);
    cudaGetSymbolAddress((void**)&dinv, g_dinv);
    cudaGetSymbolAddress((void**)&counts, g_counts);
    cudaGetSymbolAddress((void**)&rowptr, g_rowptr);
    cudaGetSymbolAddress((void**)&cursor, g_cursor);
    cudaGetSymbolAddress((void**)&csrc, g_csrc);

    float* out     = (float*)d_out;
    float* out_mu  = out + (size_t)G * dout;
    float* out_std = out_mu + (size_t)N * dl;
    float* out_y   = out_std + (size_t)N * dl;

    const int* src = ei;
    const int* dst = ei + E;

    // enable >48KB dynamic smem on the WMMA kernel templates (idempotent)
    cudaFuncSetAttribute(wgemm_k<0>, cudaFuncAttributeMaxDynamicSharedMemorySize, SMEM_BYTES);
    cudaFuncSetAttribute(wgemm_k<1>, cudaFuncAttributeMaxDynamicSharedMemorySize, SMEM_BYTES);
    cudaFuncSetAttribute(wgemm_k<2>, cudaFuncAttributeMaxDynamicSharedMemorySize, SMEM_BYTES);
    cudaFuncSetAttribute(wgemm_k<3>, cudaFuncAttributeMaxDynamicSharedMemorySize, SMEM_BYTES);

    // --- CSR + normalization ---
    cudaMemsetAsync(counts, 0, (size_t)N * sizeof(int));
    count_deg_k<<<(E + 255) / 256, 256>>>(dst, E, counts);
    scan_k<<<1, 1024>>>(counts, rowptr, cursor, N);
    dinv_k<<<(N + 255) / 256, 256>>>(counts, dinv, N);
    fill_csr_k<<<(E + 255) / 256, 256>>>(src, dst, E, cursor, csrc);

    const int gx = (N + 127) / 128;

    // --- input layer: h = sigmoid(x @ W_in + b_in) ---
    wgemm_k<1><<<dim3(gx, 1), TBS, SMEM_BYTES>>>(x, W_in, b_in, h, N, din, dl, dl, dl);

    // --- K hops ---
    for (int i = 0; i < Khops; i++) {
        wgemm_k<0><<<dim3(gx, 1), TBS, SMEM_BYTES>>>(h, W_gcn, (const float*)nullptr,
                                                     bufA, N, dl, dl, dl, dl);
        agg_k<<<N, 128>>>(bufA, bufB, rowptr, csrc, dinv, b_gcn, N);
        const float* cur = bufB;
        float* nxt = bufA;
        for (int j = 0; j < 5; j++) {
            wgemm_k<1><<<dim3(gx, 1), TBS, SMEM_BYTES>>>(
                cur, W_enc + (size_t)j * dl * dl, b_enc + (size_t)j * dl, nxt, N, dl, dl, dl, dl);
            const float* tmp = cur;
            cur = nxt;
            nxt = (float*)tmp;
        }
        wgemm_k<0><<<dim3(gx, 1), TBS, SMEM_BYTES>>>(cur, W_mu, b_mu, out_mu, N, dl, dl, dl, dl);
        wgemm_k<3><<<dim3(gx, 1), TBS, SMEM_BYTES>>>(cur, W_std, b_std, out_std, N, dl, dl, dl, dl);
        reparam_k<<<((size_t)N * dl + 255) / 256, 256>>>(out_mu, out_std,
                                                         eps + (size_t)i * N * dl, h, N * dl);
    }

    // --- decoder MLP (relu) ---
    int dd[6] = {dl, in_sizes[16], in_sizes[18], in_sizes[20], in_sizes[22], in_sizes[24]};
    wgemm_k<2><<<dim3(gx, 2), TBS, SMEM_BYTES>>>(h,    Wd[0], bd[0], bufA, N, dd[0], dd[1], dd[1], dd[1]);
    wgemm_k<2><<<dim3(gx, 1), TBS, SMEM_BYTES>>>(bufA, Wd[1], bd[1], bufB, N, dd[1], dd[2], dd[2], dd[2]);
    wgemm_k<2><<<dim3(gx, 1), TBS, SMEM_BYTES>>>(bufB, Wd[2], bd[2], bufA, N, dd[2], dd[3], dd[3], dd[3]);
    wgemm_k<2><<<dim3(gx, 1), TBS, SMEM_BYTES>>>(bufA, Wd[3], bd[3], bufB, N, dd[3], dd[4], dd[4], dd[4]);
    wgemm_k<2><<<dim3(gx, 1), TBS, SMEM_BYTES>>>(bufB, Wd[4], bd[4], bufA, N, dd[4], dd[5], dd[5], dd[5]);
    // yp = sigmoid(d @ Wo + bo)  [N, dout]
    wgemm_k<1><<<dim3(gx, 1), TBS, SMEM_BYTES>>>(bufA, Wo, bo, bufB, N, dd[5], dout, dout, dout);

    // --- pooling + y passthrough ---
    pool_k<<<G, 256>>>(bufB, bids, out, N, dout);
    cudaMemcpyAsync(out_y, y, (size_t)G * dout * sizeof(float), cudaMemcpyDeviceToDevice);
}

// round 12
// speedup vs baseline: 1.5998x; 1.1225x over previous
#include <cuda_runtime.h>
#include <cstdint>
#include <math.h>
#include <mma.h>
#include <cuda_fp16.h>

using namespace nvcuda;

#define DLC 128
#define TBS 256
static const int N_MAX = 50000;
static const int E_MAX = 800000;

// ---------------- static device scratch ----------------
__device__ float g_h   [(size_t)N_MAX * DLC];
__device__ float g_bufA[(size_t)N_MAX * 256];
__device__ float g_bufB[(size_t)N_MAX * 256];
__device__ int   g_counts[N_MAX];
__device__ int   g_rowptr[N_MAX + 1];
__device__ int   g_cursor[N_MAX];
__device__ int   g_csrc  [E_MAX];
__device__ float g_dinv  [N_MAX];

// ---------------- WMMA fp16 GEMM (fp32 accumulate) ----------------
// C[M,Ntrue] = act(A[M,K] @ W[K,Nout] + bias), A,W fp32 in gmem, converted to half in SMEM.
// Block tile 128x128, BK=64, 8 warps in 4x2, warp tile 32x64 of 16x16x16 fragments.
#define BM 128
#define BN 128
#define BKH 64
#define LDAH 72   // halves (144B, mult of 16B)
#define LDBH 136  // halves (272B, mult of 16B)
#define LDCS 132  // floats
// dynamic smem (bytes): As half[128*72] | Ws half[64*136] | Cs float[128*132]
#define OFF_WS_H (128 * LDAH)                 // in halves
#define OFF_CS_B ((OFF_WS_H + BKH * LDBH) * 2)
#define SMEM_BYTES (OFF_CS_B + 128 * LDCS * 4)

__device__ __forceinline__ float apply_act(float z, int ACT) {
    if (ACT == 1) return 1.0f / (1.0f + __expf(-z));
    if (ACT == 2) return fmaxf(z, 0.0f);
    if (ACT == 3) {
        float t = z - 5.0f;
        return fmaxf(t, 0.0f) + log1pf(__expf(-fabsf(t)));
    }
    return z;
}

template <int ACT>
__global__ __launch_bounds__(TBS, 2)
void wgemm_k(const float* __restrict__ A, const float* __restrict__ W,
             const float* __restrict__ bias, float* __restrict__ C,
             int M, int K, int Nout, int Ntrue, int ldC) {
    extern __shared__ char smraw[];
    __half* As = (__half*)smraw;
    __half* Ws = As + OFF_WS_H;
    float*  Cs = (float*)(smraw + OFF_CS_B);

    const int tid = threadIdx.x;
    const int wid = tid >> 5;
    const int mBase = blockIdx.x * BM;
    const int colBase = blockIdx.y * BN;
    const int warpRow = wid & 3;   // 0..3 -> 32 rows each
    const int warpCol = wid >> 2;  // 0..1 -> 64 cols each

    wmma::fragment<wmma::accumulator, 16, 16, 16, float> acc[2][4];
#pragma unroll
    for (int i = 0; i < 2; i++)
#pragma unroll
        for (int j = 0; j < 4; j++) wmma::fill_fragment(acc[i][j], 0.0f);

    // loader indices: A tile 128x64 (2 thr/row, 32 floats each), W tile 64x128 (4 thr/row)
    const int ar  = tid >> 1;
    const int ac0 = (tid & 1) * 32;
    const int wr  = tid >> 2;
    const int wc0 = (tid & 3) * 32;
    const bool wVec = ((Nout & 3) == 0);
    const bool aVec = ((K & 3) == 0);

    const int nch = (K + BKH - 1) / BKH;
    for (int ch = 0; ch < nch; ch++) {
        const int k0 = ch * BKH;
        const int kc = min(BKH, K - k0);
        // --- A tile -> half ---
        {
            const int gr = mBase + ar;
            const bool rok = (gr < M);
            const float* Arow = A + (size_t)gr * K + k0;
            __half* dst = As + ar * LDAH + ac0;
#pragma unroll
            for (int i = 0; i < 8; i++) {
                int c = ac0 + i * 4;
                float4 v = make_float4(0.f, 0.f, 0.f, 0.f);
                if (rok && aVec && (c + 3 < kc)) v = *(const float4*)(Arow + c);
                else if (rok) {
                    if (c + 0 < kc) v.x = Arow[c + 0];
                    if (c + 1 < kc) v.y = Arow[c + 1];
                    if (c + 2 < kc) v.z = Arow[c + 2];
                    if (c + 3 < kc) v.w = Arow[c + 3];
                }
                ((half2*)(dst + i * 4))[0] = __floats2half2_rn(v.x, v.y);
                ((half2*)(dst + i * 4))[1] = __floats2half2_rn(v.z, v.w);
            }
        }
        // --- W tile -> half ---
        {
            const int kr = k0 + wr;
            const bool kok = (kr < K);
            const float* Wrow = W + (size_t)kr * Nout + colBase;
            __half* dst = Ws + wr * LDBH + wc0;
#pragma unroll
            for (int i = 0; i < 8; i++) {
                int c = wc0 + i * 4;
                int gc = colBase + c;
                float4 v = make_float4(0.f, 0.f, 0.f, 0.f);
                if (kok && wVec && (gc + 3 < Nout)) v = *(const float4*)(Wrow + c);
                else if (kok) {
                    if (gc + 0 < Nout) v.x = Wrow[c + 0];
                    if (gc + 1 < Nout) v.y = Wrow[c + 1];
                    if (gc + 2 < Nout) v.z = Wrow[c + 2];
                    if (gc + 3 < Nout) v.w = Wrow[c + 3];
                }
                ((half2*)(dst + i * 4))[0] = __floats2half2_rn(v.x, v.y);
                ((half2*)(dst + i * 4))[1] = __floats2half2_rn(v.z, v.w);
            }
        }
        __syncthreads();

        const int ks = (kc + 15) >> 4;  // all K dims are multiples of 16
        for (int kk = 0; kk < ks; kk++) {
            wmma::fragment<wmma::matrix_a, 16, 16, 16, __half, wmma::row_major> af[2];
            wmma::fragment<wmma::matrix_b, 16, 16, 16, __half, wmma::row_major> bf[4];
#pragma unroll
            for (int i = 0; i < 2; i++)
                wmma::load_matrix_sync(af[i], As + (warpRow * 32 + i * 16) * LDAH + kk * 16, LDAH);
#pragma unroll
            for (int j = 0; j < 4; j++)
                wmma::load_matrix_sync(bf[j], Ws + (kk * 16) * LDBH + warpCol * 64 + j * 16, LDBH);
#pragma unroll
            for (int i = 0; i < 2; i++)
#pragma unroll
                for (int j = 0; j < 4; j++)
                    wmma::mma_sync(acc[i][j], af[i], bf[j], acc[i][j]);
        }
        __syncthreads();
    }

    // --- epilogue: fragments -> SMEM -> activation -> gmem ---
#pragma unroll
    for (int i = 0; i < 2; i++)
#pragma unroll
        for (int j = 0; j < 4; j++)
            wmma::store_matrix_sync(Cs + (warpRow * 32 + i * 16) * LDCS + warpCol * 64 + j * 16,
                                    acc[i][j], LDCS, wmma::mem_row_major);
    __syncthreads();

    {
        const int r = tid >> 1;
        const int ch2 = (tid & 1) * 64;
        const int gr = mBase + r;
        if (gr < M) {
            const int colRem = Ntrue - colBase - ch2;  // may be <= 0
            float* Crow = C + (size_t)gr * ldC + colBase + ch2;
            const float* Srow = Cs + r * LDCS + ch2;
            if (colRem >= 64 && ((ldC & 3) == 0)) {
#pragma unroll
                for (int c = 0; c < 64; c += 4) {
                    float4 v;
                    v.x = apply_act(Srow[c + 0] + (bias ? __ldg(bias + colBase + ch2 + c + 0) : 0.f), ACT);
                    v.y = apply_act(Srow[c + 1] + (bias ? __ldg(bias + colBase + ch2 + c + 1) : 0.f), ACT);
                    v.z = apply_act(Srow[c + 2] + (bias ? __ldg(bias + colBase + ch2 + c + 2) : 0.f), ACT);
                    v.w = apply_act(Srow[c + 3] + (bias ? __ldg(bias + colBase + ch2 + c + 3) : 0.f), ACT);
                    *(float4*)(Crow + c) = v;
                }
            } else {
                for (int c = 0; c < 64 && c < colRem; c++) {
                    float z = Srow[c] + (bias ? __ldg(bias + colBase + ch2 + c) : 0.f);
                    Crow[c] = apply_act(z, ACT);
                }
            }
        }
    }
}

// ---------------- graph/CSR kernels ----------------
__global__ void count_deg_k(const int* __restrict__ dst, int E, int* __restrict__ counts) {
    int e = blockIdx.x * blockDim.x + threadIdx.x;
    if (e < E) atomicAdd(&counts[dst[e]], 1);
}

__global__ void scan_k(const int* __restrict__ counts, int* __restrict__ rowptr,
                       int* __restrict__ cursor, int n) {
    __shared__ int sm[1024];
    int tid = threadIdx.x;
    int chunk = (n + 1023) >> 10;
    int s = tid * chunk;
    int e = min(s + chunk, n);
    int sum = 0;
    for (int i = s; i < e && i < n; i++) sum += counts[i];
    sm[tid] = sum;
    __syncthreads();
    for (int off = 1; off < 1024; off <<= 1) {
        int v = (tid >= off) ? sm[tid - off] : 0;
        __syncthreads();
        sm[tid] += v;
        __syncthreads();
    }
    int run = (tid > 0) ? sm[tid - 1] : 0;
    for (int i = s; i < e && i < n; i++) {
        rowptr[i] = run;
        cursor[i] = run;
        run += counts[i];
    }
    if (e >= n) rowptr[n] = run;
}

__global__ void dinv_k(const int* __restrict__ counts, float* __restrict__ dinv, int n) {
    int i = blockIdx.x * blockDim.x + threadIdx.x;
    if (i < n) dinv[i] = rsqrtf((float)counts[i] + 1.0f);
}

__global__ void fill_csr_k(const int* __restrict__ src, const int* __restrict__ dst, int E,
                           int* __restrict__ cursor, int* __restrict__ csrc) {
    int e = blockIdx.x * blockDim.x + threadIdx.x;
    if (e < E) {
        int d = dst[e];
        int p = atomicAdd(&cursor[d], 1);
        csrc[p] = src[e];
    }
}

__global__ void agg_k(const float* __restrict__ gmat, float* __restrict__ out,
                      const int* __restrict__ rowptr, const int* __restrict__ csrc,
                      const float* __restrict__ dinv, const float* __restrict__ bias, int n) {
    int node = blockIdx.x;
    int j = threadIdx.x;
    float dn = dinv[node];
    float acc = gmat[(size_t)node * DLC + j] * dn * dn + bias[j];
    int beg = rowptr[node];
    int end = rowptr[node + 1];
    for (int e = beg; e < end; e++) {
        int s = csrc[e];
        acc += gmat[(size_t)s * DLC + j] * (dinv[s] * dn);
    }
    out[(size_t)node * DLC + j] = acc;
}

__global__ void reparam_k(const float* __restrict__ mu, const float* __restrict__ sd,
                          const float* __restrict__ eps, float* __restrict__ h, int n) {
    int i = blockIdx.x * blockDim.x + threadIdx.x;
    if (i < n) h[i] = fmaf(sd[i], eps[i], mu[i]);
}

__global__ void pool_k(const float* __restrict__ yp, const int* __restrict__ bids,
                       float* __restrict__ out, int N, int dout) {
    int g = blockIdx.x;
    int lo = 0, hi = N;
    while (lo < hi) { int m = (lo + hi) >> 1; if (bids[m] < g) lo = m + 1; else hi = m; }
    int start = lo;
    lo = start; hi = N;
    while (lo < hi) { int m = (lo + hi) >> 1; if (bids[m] < g + 1) lo = m + 1; else hi = m; }
    int end = lo;

    __shared__ float sm[16];
    if (threadIdx.x < dout) sm[threadIdx.x] = 0.0f;
    __syncthreads();
    float loc[10];
#pragma unroll
    for (int f = 0; f < 10; f++) loc[f] = 0.0f;
    for (int nidx = start + threadIdx.x; nidx < end; nidx += blockDim.x) {
#pragma unroll
        for (int f = 0; f < 10; f++) loc[f] += yp[(size_t)nidx * dout + f];
    }
#pragma unroll
    for (int f = 0; f < 10; f++) atomicAdd(&sm[f], loc[f]);
    __syncthreads();
    int cnt = end - start;
    float inv = 1.0f / (float)max(cnt, 1);
    if (threadIdx.x < dout) out[(size_t)g * dout + threadIdx.x] = sm[threadIdx.x] * inv;
}

// ---------------- launch ----------------
extern "C" void kernel_launch(void* const* d_in, const int* in_sizes, int n_in,
                              void* d_out, int out_size) {
    const float* x     = (const float*)d_in[0];
    const int*   ei    = (const int*)d_in[1];
    const int*   bids  = (const int*)d_in[2];
    const float* y     = (const float*)d_in[3];
    const float* eps   = (const float*)d_in[4];
    const float* W_in  = (const float*)d_in[5];
    const float* b_in  = (const float*)d_in[6];
    const float* W_gcn = (const float*)d_in[7];
    const float* b_gcn = (const float*)d_in[8];
    const float* W_enc = (const float*)d_in[9];
    const float* b_enc = (const float*)d_in[10];
    const float* W_mu  = (const float*)d_in[11];
    const float* b_mu  = (const float*)d_in[12];
    const float* W_std = (const float*)d_in[13];
    const float* b_std = (const float*)d_in[14];
    const float* Wd[5];
    const float* bd[5];
    for (int i = 0; i < 5; i++) {
        Wd[i] = (const float*)d_in[15 + 2 * i];
        bd[i] = (const float*)d_in[16 + 2 * i];
    }
    const float* Wo = (const float*)d_in[25];
    const float* bo = (const float*)d_in[26];

    const int dl    = in_sizes[6];             // 128
    const int din   = in_sizes[5] / dl;        // 32
    const int N     = in_sizes[0] / din;       // 50000
    const int E     = in_sizes[1] / 2;         // 800000
    const int dout  = in_sizes[26];            // 10
    const int G     = in_sizes[3] / dout;      // 256
    const int Khops = in_sizes[4] / (N * dl);  // 3

    float *h, *bufA, *bufB, *dinv;
    int *counts, *rowptr, *cursor, *csrc;
    cudaGetSymbolAddress((void**)&h, g_h);
    cudaGetSymbolAddress((void**)&bufA, g_bufA);
    cudaGetSymbolAddress((void**)&bufB, g_bufB);
    cudaGetSymbolAddress((void**)&dinv, g_dinv);
    cudaGetSymbolAddress((void**)&counts, g_counts);
    cudaGetSymbolAddress((void**)&rowptr, g_rowptr);
    cudaGetSymbolAddress((void**)&cursor, g_cursor);
    cudaGetSymbolAddress((void**)&csrc, g_csrc);

    float* out     = (float*)d_out;
    float* out_mu  = out + (size_t)G * dout;
    float* out_std = out_mu + (size_t)N * dl;
    float* out_y   = out_std + (size_t)N * dl;

    const int* src = ei;
    const int* dst = ei + E;

    // enable >48KB dynamic smem on the WMMA kernel templates (idempotent)
    cudaFuncSetAttribute(wgemm_k<0>, cudaFuncAttributeMaxDynamicSharedMemorySize, SMEM_BYTES);
    cudaFuncSetAttribute(wgemm_k<1>, cudaFuncAttributeMaxDynamicSharedMemorySize, SMEM_BYTES);
    cudaFuncSetAttribute(wgemm_k<2>, cudaFuncAttributeMaxDynamicSharedMemorySize, SMEM_BYTES);
    cudaFuncSetAttribute(wgemm_k<3>, cudaFuncAttributeMaxDynamicSharedMemorySize, SMEM_BYTES);

    // --- CSR + normalization ---
    cudaMemsetAsync(counts, 0, (size_t)N * sizeof(int));
    count_deg_k<<<(E + 255) / 256, 256>>>(dst, E, counts);
    scan_k<<<1, 1024>>>(counts, rowptr, cursor, N);
    dinv_k<<<(N + 255) / 256, 256>>>(counts, dinv, N);
    fill_csr_k<<<(E + 255) / 256, 256>>>(src, dst, E, cursor, csrc);

    const int gx = (N + 127) / 128;

    // --- input layer: h = sigmoid(x @ W_in + b_in) ---
    wgemm_k<1><<<dim3(gx, 1), TBS, SMEM_BYTES>>>(x, W_in, b_in, h, N, din, dl, dl, dl);

    // --- K hops ---
    for (int i = 0; i < Khops; i++) {
        wgemm_k<0><<<dim3(gx, 1), TBS, SMEM_BYTES>>>(h, W_gcn, (const float*)nullptr,
                                                     bufA, N, dl, dl, dl, dl);
        agg_k<<<N, 128>>>(bufA, bufB, rowptr, csrc, dinv, b_gcn, N);
        const float* cur = bufB;
        float* nxt = bufA;
        for (int j = 0; j < 5; j++) {
            wgemm_k<1><<<dim3(gx, 1), TBS, SMEM_BYTES>>>(
                cur, W_enc + (size_t)j * dl * dl, b_enc + (size_t)j * dl, nxt, N, dl, dl, dl, dl);
            const float* tmp = cur;
            cur = nxt;
            nxt = (float*)tmp;
        }
        wgemm_k<0><<<dim3(gx, 1), TBS, SMEM_BYTES>>>(cur, W_mu, b_mu, out_mu, N, dl, dl, dl, dl);
        wgemm_k<3><<<dim3(gx, 1), TBS, SMEM_BYTES>>>(cur, W_std, b_std, out_std, N, dl, dl, dl, dl);
        reparam_k<<<((size_t)N * dl + 255) / 256, 256>>>(out_mu, out_std,
                                                         eps + (size_t)i * N * dl, h, N * dl);
    }

    // --- decoder MLP (relu) ---
    int dd[6] = {dl, in_sizes[16], in_sizes[18], in_sizes[20], in_sizes[22], in_sizes[24]};
    wgemm_k<2><<<dim3(gx, 2), TBS, SMEM_BYTES>>>(h,    Wd[0], bd[0], bufA, N, dd[0], dd[1], dd[1], dd[1]);
    wgemm_k<2><<<dim3(gx, 1), TBS, SMEM_BYTES>>>(bufA, Wd[1], bd[1], bufB, N, dd[1], dd[2], dd[2], dd[2]);
    wgemm_k<2><<<dim3(gx, 1), TBS, SMEM_BYTES>>>(bufB, Wd[2], bd[2], bufA, N, dd[2], dd[3], dd[3], dd[3]);
    wgemm_k<2><<<dim3(gx, 1), TBS, SMEM_BYTES>>>(bufA, Wd[3], bd[3], bufB, N, dd[3], dd[4], dd[4], dd[4]);
    wgemm_k<2><<<dim3(gx, 1), TBS, SMEM_BYTES>>>(bufB, Wd[4], bd[4], bufA, N, dd[4], dd[5], dd[5], dd[5]);
    // yp = sigmoid(d @ Wo + bo)  [N, dout]
    wgemm_k<1><<<dim3(gx, 1), TBS, SMEM_BYTES>>>(bufA, Wo, bo, bufB, N, dd[5], dout, dout, dout);

    // --- pooling + y passthrough ---
    pool_k<<<G, 256>>>(bufB, bids, out, N, dout);
    cudaMemcpyAsync(out_y, y, (size_t)G * dout * sizeof(float), cudaMemcpyDeviceToDevice);
}

// round 14
// speedup vs baseline: 1.9500x; 1.2189x over previous
#include <cuda_runtime.h>
#include <cstdint>
#include <math.h>
#include <mma.h>
#include <cuda_fp16.h>

using namespace nvcuda;

#define DLC 128
#define TBS 256
static const int N_MAX = 50000;
static const int E_MAX = 800000;

// ---------------- static device scratch ----------------
__device__ float g_h   [(size_t)N_MAX * DLC];
__device__ float g_bufA[(size_t)N_MAX * 256];
__device__ float g_bufB[(size_t)N_MAX * 256];
__device__ int   g_counts[N_MAX];
__device__ int   g_rowptr[N_MAX + 1];
__device__ int   g_cursor[N_MAX];
__device__ int   g_csrc  [E_MAX];
__device__ float g_dinv  [N_MAX];

__device__ __forceinline__ float apply_act(float z, int ACT) {
    if (ACT == 1) return 1.0f / (1.0f + __expf(-z));
    if (ACT == 2) return fmaxf(z, 0.0f);
    if (ACT == 3) {
        float t = z - 5.0f;
        return fmaxf(t, 0.0f) + log1pf(__expf(-fabsf(t)));
    }
    return z;
}

// ================= fused encoder-hop kernel =================
// Per CTA: 128-row activation block resident in SMEM (fp16).
// in (fp32, post-agg) -> 5x sigmoid(g@W_enc[j]+b) -> mu/std GEMMs -> reparam h.
// SMEM: actA/actB/Wsm half[128*136] + staging float[8][16*20]
#define FLDH 136
#define FTILE (128 * FLDH)
#define SLD 20
#define F_STAGE_OFF (3 * FTILE * 2)                 // bytes
#define F_SMEM (F_STAGE_OFF + 8 * 16 * SLD * 4)     // 104448 + 10240 = 114688

__global__ __launch_bounds__(TBS, 2)
void enc_fused_k(const float* __restrict__ gin,
                 const float* __restrict__ W_enc, const float* __restrict__ b_enc,
                 const float* __restrict__ W_mu, const float* __restrict__ b_mu,
                 const float* __restrict__ W_std, const float* __restrict__ b_std,
                 const float* __restrict__ eps_i,
                 float* __restrict__ out_mu, float* __restrict__ out_std,
                 float* __restrict__ h, int M, int dl) {
    extern __shared__ char smraw[];
    __half* actA = (__half*)smraw;
    __half* actB = actA + FTILE;
    __half* Wsm  = actB + FTILE;
    float*  stage = (float*)(smraw + F_STAGE_OFF);

    const int tid = threadIdx.x;
    const int wid = tid >> 5;
    const int lid = tid & 31;
    const int mBase = blockIdx.x * 128;
    const int warpRow = wid & 3;
    const int warpCol = wid >> 2;
    float* wstage = stage + wid * 16 * SLD;

    // ---- load input block (fp32 -> fp16) ----
    {
        const int r = tid >> 1;
        const int c0 = (tid & 1) * 64;
        const int gr = mBase + r;
        __half* dst = actA + r * FLDH + c0;
        if (gr < M) {
            const float* srow = gin + (size_t)gr * dl + c0;
#pragma unroll
            for (int i = 0; i < 16; i++) {
                float4 v = *(const float4*)(srow + i * 4);
                ((half2*)(dst + i * 4))[0] = __floats2half2_rn(v.x, v.y);
                ((half2*)(dst + i * 4))[1] = __floats2half2_rn(v.z, v.w);
            }
        } else {
#pragma unroll
            for (int i = 0; i < 32; i++) ((half2*)dst)[i] = __floats2half2_rn(0.f, 0.f);
        }
    }

    __half* cur = actA;
    __half* nxt = actB;

    // process one GEMM layer from `cur` with weight Wg/bias bg.
    // MODE 0: sigmoid -> nxt (fp16). MODE 1: write fp32 gout (no act). MODE 2: softplus(z-5) -> gout.
    auto do_layer = [&](const float* Wg, const float* bg, int MODE, float* gout) {
        // load weights [dl x dl] fp32 -> fp16 SMEM
        {
            const int r = tid >> 1;
            const int c0 = (tid & 1) * 64;
            const float* srow = Wg + (size_t)r * dl + c0;
            __half* dst = Wsm + r * FLDH + c0;
#pragma unroll
            for (int i = 0; i < 16; i++) {
                float4 v = *(const float4*)(srow + i * 4);
                ((half2*)(dst + i * 4))[0] = __floats2half2_rn(v.x, v.y);
                ((half2*)(dst + i * 4))[1] = __floats2half2_rn(v.z, v.w);
            }
        }
        __syncthreads();

        wmma::fragment<wmma::accumulator, 16, 16, 16, float> acc[2][4];
#pragma unroll
        for (int i = 0; i < 2; i++)
#pragma unroll
            for (int j = 0; j < 4; j++) wmma::fill_fragment(acc[i][j], 0.0f);

#pragma unroll
        for (int kk = 0; kk < 8; kk++) {
            wmma::fragment<wmma::matrix_a, 16, 16, 16, __half, wmma::row_major> af[2];
            wmma::fragment<wmma::matrix_b, 16, 16, 16, __half, wmma::row_major> bf[4];
#pragma unroll
            for (int i = 0; i < 2; i++)
                wmma::load_matrix_sync(af[i], cur + (warpRow * 32 + i * 16) * FLDH + kk * 16, FLDH);
#pragma unroll
            for (int j = 0; j < 4; j++)
                wmma::load_matrix_sync(bf[j], Wsm + (kk * 16) * FLDH + warpCol * 64 + j * 16, FLDH);
#pragma unroll
            for (int i = 0; i < 2; i++)
#pragma unroll
                for (int j = 0; j < 4; j++)
                    wmma::mma_sync(acc[i][j], af[i], bf[j], acc[i][j]);
        }

        // epilogue via per-warp staging (16x16 at a time)
        const int er = lid >> 1;            // 0..15
        const int ec = (lid & 1) * 8;       // 0 or 8
#pragma unroll
        for (int i = 0; i < 2; i++) {
#pragma unroll
            for (int j = 0; j < 4; j++) {
                wmma::store_matrix_sync(wstage, acc[i][j], SLD, wmma::mem_row_major);
                __syncwarp();
                const int rw = warpRow * 32 + i * 16 + er;
                const int cw = warpCol * 64 + j * 16 + ec;
                const int gr = mBase + rw;
                float z[8];
#pragma unroll
                for (int u = 0; u < 8; u++)
                    z[u] = wstage[er * SLD + ec + u] + __ldg(bg + cw + u);
                if (MODE == 0) {
#pragma unroll
                    for (int u = 0; u < 8; u++) z[u] = 1.0f / (1.0f + __expf(-z[u]));
                    half2 p0 = __floats2half2_rn(z[0], z[1]);
                    half2 p1 = __floats2half2_rn(z[2], z[3]);
                    half2 p2 = __floats2half2_rn(z[4], z[5]);
                    half2 p3 = __floats2half2_rn(z[6], z[7]);
                    half2* d = (half2*)(nxt + rw * FLDH + cw);
                    d[0] = p0; d[1] = p1; d[2] = p2; d[3] = p3;
                } else {
                    if (MODE == 2) {
#pragma unroll
                        for (int u = 0; u < 8; u++) {
                            float t = z[u] - 5.0f;
                            z[u] = fmaxf(t, 0.0f) + log1pf(__expf(-fabsf(t)));
                        }
                    }
                    if (gr < M) {
                        float* d = gout + (size_t)gr * dl + cw;
                        *(float4*)(d + 0) = make_float4(z[0], z[1], z[2], z[3]);
                        *(float4*)(d + 4) = make_float4(z[4], z[5], z[6], z[7]);
                    }
                }
                __syncwarp();
            }
        }
        __syncthreads();  // all warps done with Wsm/cur before next layer overwrites
    };

    // 5 sigmoid layers
    for (int l = 0; l < 5; l++) {
        do_layer(W_enc + (size_t)l * dl * dl, b_enc + (size_t)l * dl, 0, nullptr);
        __half* t = cur; cur = nxt; nxt = t;
    }
    // mu and std from same activation `cur`
    do_layer(W_mu, b_mu, 1, out_mu);
    do_layer(W_std, b_std, 2, out_std);

    // reparam: h = mu + std * eps  (block-local gmem reuse)
    __threadfence_block();
    __syncthreads();
    {
        const int r = tid >> 1;
        const int c0 = (tid & 1) * 64;
        const int gr = mBase + r;
        if (gr < M) {
            const size_t base = (size_t)gr * dl + c0;
#pragma unroll
            for (int i = 0; i < 16; i++) {
                float4 m4 = *(const float4*)(out_mu + base + i * 4);
                float4 s4 = *(const float4*)(out_std + base + i * 4);
                float4 e4 = *(const float4*)(eps_i + base + i * 4);
                float4 r4;
                r4.x = fmaf(s4.x, e4.x, m4.x);
                r4.y = fmaf(s4.y, e4.y, m4.y);
                r4.z = fmaf(s4.z, e4.z, m4.z);
                r4.w = fmaf(s4.w, e4.w, m4.w);
                *(float4*)(h + base + i * 4) = r4;
            }
        }
    }
}

// ---------------- WMMA fp16 GEMM (fp32 accumulate) ----------------
#define BM 128
#define BN 128
#define BKH 64
#define LDAH 72
#define LDBH 136
#define LDCS 132
#define OFF_WS_H (128 * LDAH)
#define OFF_CS_B ((OFF_WS_H + BKH * LDBH) * 2)
#define SMEM_BYTES (OFF_CS_B + 128 * LDCS * 4)

template <int ACT>
__global__ __launch_bounds__(TBS, 2)
void wgemm_k(const float* __restrict__ A, const float* __restrict__ W,
             const float* __restrict__ bias, float* __restrict__ C,
             int M, int K, int Nout, int Ntrue, int ldC) {
    extern __shared__ char smraw[];
    __half* As = (__half*)smraw;
    __half* Ws = As + OFF_WS_H;
    float*  Cs = (float*)(smraw + OFF_CS_B);

    const int tid = threadIdx.x;
    const int wid = tid >> 5;
    const int mBase = blockIdx.x * BM;
    const int colBase = blockIdx.y * BN;
    const int warpRow = wid & 3;
    const int warpCol = wid >> 2;

    wmma::fragment<wmma::accumulator, 16, 16, 16, float> acc[2][4];
#pragma unroll
    for (int i = 0; i < 2; i++)
#pragma unroll
        for (int j = 0; j < 4; j++) wmma::fill_fragment(acc[i][j], 0.0f);

    const int ar  = tid >> 1;
    const int ac0 = (tid & 1) * 32;
    const int wr  = tid >> 2;
    const int wc0 = (tid & 3) * 32;
    const bool wVec = ((Nout & 3) == 0);
    const bool aVec = ((K & 3) == 0);

    const int nch = (K + BKH - 1) / BKH;
    for (int ch = 0; ch < nch; ch++) {
        const int k0 = ch * BKH;
        const int kc = min(BKH, K - k0);
        {
            const int gr = mBase + ar;
            const bool rok = (gr < M);
            const float* Arow = A + (size_t)gr * K + k0;
            __half* dst = As + ar * LDAH + ac0;
#pragma unroll
            for (int i = 0; i < 8; i++) {
                int c = ac0 + i * 4;
                float4 v = make_float4(0.f, 0.f, 0.f, 0.f);
                if (rok && aVec && (c + 3 < kc)) v = *(const float4*)(Arow + c);
                else if (rok) {
                    if (c + 0 < kc) v.x = Arow[c + 0];
                    if (c + 1 < kc) v.y = Arow[c + 1];
                    if (c + 2 < kc) v.z = Arow[c + 2];
                    if (c + 3 < kc) v.w = Arow[c + 3];
                }
                ((half2*)(dst + i * 4))[0] = __floats2half2_rn(v.x, v.y);
                ((half2*)(dst + i * 4))[1] = __floats2half2_rn(v.z, v.w);
            }
        }
        {
            const int kr = k0 + wr;
            const bool kok = (kr < K);
            const float* Wrow = W + (size_t)kr * Nout + colBase;
            __half* dst = Ws + wr * LDBH + wc0;
#pragma unroll
            for (int i = 0; i < 8; i++) {
                int c = wc0 + i * 4;
                int gc = colBase + c;
                float4 v = make_float4(0.f, 0.f, 0.f, 0.f);
                if (kok && wVec && (gc + 3 < Nout)) v = *(const float4*)(Wrow + c);
                else if (kok) {
                    if (gc + 0 < Nout) v.x = Wrow[c + 0];
                    if (gc + 1 < Nout) v.y = Wrow[c + 1];
                    if (gc + 2 < Nout) v.z = Wrow[c + 2];
                    if (gc + 3 < Nout) v.w = Wrow[c + 3];
                }
                ((half2*)(dst + i * 4))[0] = __floats2half2_rn(v.x, v.y);
                ((half2*)(dst + i * 4))[1] = __floats2half2_rn(v.z, v.w);
            }
        }
        __syncthreads();

        const int ks = (kc + 15) >> 4;
        for (int kk = 0; kk < ks; kk++) {
            wmma::fragment<wmma::matrix_a, 16, 16, 16, __half, wmma::row_major> af[2];
            wmma::fragment<wmma::matrix_b, 16, 16, 16, __half, wmma::row_major> bf[4];
#pragma unroll
            for (int i = 0; i < 2; i++)
                wmma::load_matrix_sync(af[i], As + (warpRow * 32 + i * 16) * LDAH + kk * 16, LDAH);
#pragma unroll
            for (int j = 0; j < 4; j++)
                wmma::load_matrix_sync(bf[j], Ws + (kk * 16) * LDBH + warpCol * 64 + j * 16, LDBH);
#pragma unroll
            for (int i = 0; i < 2; i++)
#pragma unroll
                for (int j = 0; j < 4; j++)
                    wmma::mma_sync(acc[i][j], af[i], bf[j], acc[i][j]);
        }
        __syncthreads();
    }

#pragma unroll
    for (int i = 0; i < 2; i++)
#pragma unroll
        for (int j = 0; j < 4; j++)
            wmma::store_matrix_sync(Cs + (warpRow * 32 + i * 16) * LDCS + warpCol * 64 + j * 16,
                                    acc[i][j], LDCS, wmma::mem_row_major);
    __syncthreads();

    {
        const int r = tid >> 1;
        const int ch2 = (tid & 1) * 64;
        const int gr = mBase + r;
        if (gr < M) {
            const int colRem = Ntrue - colBase - ch2;
            float* Crow = C + (size_t)gr * ldC + colBase + ch2;
            const float* Srow = Cs + r * LDCS + ch2;
            if (colRem >= 64 && ((ldC & 3) == 0)) {
#pragma unroll
                for (int c = 0; c < 64; c += 4) {
                    float4 v;
                    v.x = apply_act(Srow[c + 0] + (bias ? __ldg(bias + colBase + ch2 + c + 0) : 0.f), ACT);
                    v.y = apply_act(Srow[c + 1] + (bias ? __ldg(bias + colBase + ch2 + c + 1) : 0.f), ACT);
                    v.z = apply_act(Srow[c + 2] + (bias ? __ldg(bias + colBase + ch2 + c + 2) : 0.f), ACT);
                    v.w = apply_act(Srow[c + 3] + (bias ? __ldg(bias + colBase + ch2 + c + 3) : 0.f), ACT);
                    *(float4*)(Crow + c) = v;
                }
            } else {
                for (int c = 0; c < 64 && c < colRem; c++) {
                    float z = Srow[c] + (bias ? __ldg(bias + colBase + ch2 + c) : 0.f);
                    Crow[c] = apply_act(z, ACT);
                }
            }
        }
    }
}

// ---------------- graph/CSR kernels ----------------
__global__ void count_deg_k(const int* __restrict__ dst, int E, int* __restrict__ counts) {
    int e = blockIdx.x * blockDim.x + threadIdx.x;
    if (e < E) atomicAdd(&counts[dst[e]], 1);
}

__global__ void scan_k(const int* __restrict__ counts, int* __restrict__ rowptr,
                       int* __restrict__ cursor, int n) {
    __shared__ int sm[1024];
    int tid = threadIdx.x;
    int chunk = (n + 1023) >> 10;
    int s = tid * chunk;
    int e = min(s + chunk, n);
    int sum = 0;
    for (int i = s; i < e && i < n; i++) sum += counts[i];
    sm[tid] = sum;
    __syncthreads();
    for (int off = 1; off < 1024; off <<= 1) {
        int v = (tid >= off) ? sm[tid - off] : 0;
        __syncthreads();
        sm[tid] += v;
        __syncthreads();
    }
    int run = (tid > 0) ? sm[tid - 1] : 0;
    for (int i = s; i < e && i < n; i++) {
        rowptr[i] = run;
        cursor[i] = run;
        run += counts[i];
    }
    if (e >= n) rowptr[n] = run;
}

__global__ void dinv_k(const int* __restrict__ counts, float* __restrict__ dinv, int n) {
    int i = blockIdx.x * blockDim.x + threadIdx.x;
    if (i < n) dinv[i] = rsqrtf((float)counts[i] + 1.0f);
}

__global__ void fill_csr_k(const int* __restrict__ src, const int* __restrict__ dst, int E,
                           int* __restrict__ cursor, int* __restrict__ csrc) {
    int e = blockIdx.x * blockDim.x + threadIdx.x;
    if (e < E) {
        int d = dst[e];
        int p = atomicAdd(&cursor[d], 1);
        csrc[p] = src[e];
    }
}

__global__ void agg_k(const float* __restrict__ gmat, float* __restrict__ out,
                      const int* __restrict__ rowptr, const int* __restrict__ csrc,
                      const float* __restrict__ dinv, const float* __restrict__ bias, int n) {
    int node = blockIdx.x;
    int j = threadIdx.x;
    float dn = dinv[node];
    float acc = gmat[(size_t)node * DLC + j] * dn * dn + bias[j];
    int beg = rowptr[node];
    int end = rowptr[node + 1];
    for (int e = beg; e < end; e++) {
        int s = csrc[e];
        acc += gmat[(size_t)s * DLC + j] * (dinv[s] * dn);
    }
    out[(size_t)node * DLC + j] = acc;
}

__global__ void pool_k(const float* __restrict__ yp, const int* __restrict__ bids,
                       float* __restrict__ out, int N, int dout) {
    int g = blockIdx.x;
    int lo = 0, hi = N;
    while (lo < hi) { int m = (lo + hi) >> 1; if (bids[m] < g) lo = m + 1; else hi = m; }
    int start = lo;
    lo = start; hi = N;
    while (lo < hi) { int m = (lo + hi) >> 1; if (bids[m] < g + 1) lo = m + 1; else hi = m; }
    int end = lo;

    __shared__ float sm[16];
    if (threadIdx.x < dout) sm[threadIdx.x] = 0.0f;
    __syncthreads();
    float loc[10];
#pragma unroll
    for (int f = 0; f < 10; f++) loc[f] = 0.0f;
    for (int nidx = start + threadIdx.x; nidx < end; nidx += blockDim.x) {
#pragma unroll
        for (int f = 0; f < 10; f++) loc[f] += yp[(size_t)nidx * dout + f];
    }
#pragma unroll
    for (int f = 0; f < 10; f++) atomicAdd(&sm[f], loc[f]);
    __syncthreads();
    int cnt = end - start;
    float inv = 1.0f / (float)max(cnt, 1);
    if (threadIdx.x < dout) out[(size_t)g * dout + threadIdx.x] = sm[threadIdx.x] * inv;
}

// ---------------- launch ----------------
extern "C" void kernel_launch(void* const* d_in, const int* in_sizes, int n_in,
                              void* d_out, int out_size) {
    const float* x     = (const float*)d_in[0];
    const int*   ei    = (const int*)d_in[1];
    const int*   bids  = (const int*)d_in[2];
    const float* y     = (const float*)d_in[3];
    const float* eps   = (const float*)d_in[4];
    const float* W_in  = (const float*)d_in[5];
    const float* b_in  = (const float*)d_in[6];
    const float* W_gcn = (const float*)d_in[7];
    const float* b_gcn = (const float*)d_in[8];
    const float* W_enc = (const float*)d_in[9];
    const float* b_enc = (const float*)d_in[10];
    const float* W_mu  = (const float*)d_in[11];
    const float* b_mu  = (const float*)d_in[12];
    const float* W_std = (const float*)d_in[13];
    const float* b_std = (const float*)d_in[14];
    const float* Wd[5];
    const float* bd[5];
    for (int i = 0; i < 5; i++) {
        Wd[i] = (const float*)d_in[15 + 2 * i];
        bd[i] = (const float*)d_in[16 + 2 * i];
    }
    const float* Wo = (const float*)d_in[25];
    const float* bo = (const float*)d_in[26];

    const int dl    = in_sizes[6];             // 128
    const int din   = in_sizes[5] / dl;        // 32
    const int N     = in_sizes[0] / din;       // 50000
    const int E     = in_sizes[1] / 2;         // 800000
    const int dout  = in_sizes[26];            // 10
    const int G     = in_sizes[3] / dout;      // 256
    const int Khops = in_sizes[4] / (N * dl);  // 3

    float *h, *bufA, *bufB, *dinv;
    int *counts, *rowptr, *cursor, *csrc;
    cudaGetSymbolAddress((void**)&h, g_h);
    cudaGetSymbolAddress((void**)&bufA, g_bufA);
    cudaGetSymbolAddress((void**)&bufB, g_bufB);
    cudaGetSymbolAddress((void**)&dinv, g_dinv);
    cudaGetSymbolAddress((void**)&counts, g_counts);
    cudaGetSymbolAddress((void**)&rowptr, g_rowptr);
    cudaGetSymbolAddress((void**)&cursor, g_cursor);
    cudaGetSymbolAddress((void**)&csrc, g_csrc);

    float* out     = (float*)d_out;
    float* out_mu  = out + (size_t)G * dout;
    float* out_std = out_mu + (size_t)N * dl;
    float* out_y   = out_std + (size_t)N * dl;

    const int* src = ei;
    const int* dst = ei + E;

    cudaFuncSetAttribute(wgemm_k<0>, cudaFuncAttributeMaxDynamicSharedMemorySize, SMEM_BYTES);
    cudaFuncSetAttribute(wgemm_k<1>, cudaFuncAttributeMaxDynamicSharedMemorySize, SMEM_BYTES);
    cudaFuncSetAttribute(wgemm_k<2>, cudaFuncAttributeMaxDynamicSharedMemorySize, SMEM_BYTES);
    cudaFuncSetAttribute(wgemm_k<3>, cudaFuncAttributeMaxDynamicSharedMemorySize, SMEM_BYTES);
    cudaFuncSetAttribute(enc_fused_k, cudaFuncAttributeMaxDynamicSharedMemorySize, F_SMEM);

    // --- CSR + normalization ---
    cudaMemsetAsync(counts, 0, (size_t)N * sizeof(int));
    count_deg_k<<<(E + 255) / 256, 256>>>(dst, E, counts);
    scan_k<<<1, 1024>>>(counts, rowptr, cursor, N);
    dinv_k<<<(N + 255) / 256, 256>>>(counts, dinv, N);
    fill_csr_k<<<(E + 255) / 256, 256>>>(src, dst, E, cursor, csrc);

    const int gx = (N + 127) / 128;

    // --- input layer: h = sigmoid(x @ W_in + b_in) ---
    wgemm_k<1><<<dim3(gx, 1), TBS, SMEM_BYTES>>>(x, W_in, b_in, h, N, din, dl, dl, dl);

    // --- K hops: gcn GEMM -> edge aggregation -> fused encoder chain ---
    for (int i = 0; i < Khops; i++) {
        wgemm_k<0><<<dim3(gx, 1), TBS, SMEM_BYTES>>>(h, W_gcn, (const float*)nullptr,
                                                     bufA, N, dl, dl, dl, dl);
        agg_k<<<N, 128>>>(bufA, bufB, rowptr, csrc, dinv, b_gcn, N);
        enc_fused_k<<<gx, TBS, F_SMEM>>>(bufB, W_enc, b_enc, W_mu, b_mu, W_std, b_std,
                                         eps + (size_t)i * N * dl, out_mu, out_std, h, N, dl);
    }

    // --- decoder MLP (relu) ---
    int dd[6] = {dl, in_sizes[16], in_sizes[18], in_sizes[20], in_sizes[22], in_sizes[24]};
    wgemm_k<2><<<dim3(gx, 2), TBS, SMEM_BYTES>>>(h,    Wd[0], bd[0], bufA, N, dd[0], dd[1], dd[1], dd[1]);
    wgemm_k<2><<<dim3(gx, 1), TBS, SMEM_BYTES>>>(bufA, Wd[1], bd[1], bufB, N, dd[1], dd[2], dd[2], dd[2]);
    wgemm_k<2><<<dim3(gx, 1), TBS, SMEM_BYTES>>>(bufB, Wd[2], bd[2], bufA, N, dd[2], dd[3], dd[3], dd[3]);
    wgemm_k<2><<<dim3(gx, 1), TBS, SMEM_BYTES>>>(bufA, Wd[3], bd[3], bufB, N, dd[3], dd[4], dd[4], dd[4]);
    wgemm_k<2><<<dim3(gx, 1), TBS, SMEM_BYTES>>>(bufB, Wd[4], bd[4], bufA, N, dd[4], dd[5], dd[5], dd[5]);
    wgemm_k<1><<<dim3(gx, 1), TBS, SMEM_BYTES>>>(bufA, Wo, bo, bufB, N, dd[5], dout, dout, dout);

    // --- pooling + y passthrough ---
    pool_k<<<G, 256>>>(bufB, bids, out, N, dout);
    cudaMemcpyAsync(out_y, y, (size_t)G * dout * sizeof(float), cudaMemcpyDeviceToDevice);
}

// round 16
// speedup vs baseline: 2.0329x; 1.0425x over previous
#include <cuda_runtime.h>
#include <cstdint>
#include <math.h>
#include <mma.h>
#include <cuda_fp16.h>

using namespace nvcuda;

#define DLC 128
#define TBS 256
static const int N_MAX = 50000;
static const int E_MAX = 800000;

// ---------------- static device scratch ----------------
__device__ float g_h   [(size_t)N_MAX * DLC];
__device__ float g_bufA[(size_t)N_MAX * 256];
__device__ float g_bufB[(size_t)N_MAX * 256];
__device__ int   g_counts[N_MAX];
__device__ int   g_rowptr[N_MAX + 1];
__device__ int   g_cursor[N_MAX];
__device__ int   g_csrc  [E_MAX];
__device__ float g_dinv  [N_MAX];

__device__ __forceinline__ float apply_act(float z, int ACT) {
    if (ACT == 1) return 1.0f / (1.0f + __expf(-z));
    if (ACT == 2) return fmaxf(z, 0.0f);
    if (ACT == 3) {
        float t = z - 5.0f;
        return fmaxf(t, 0.0f) + log1pf(__expf(-fabsf(t)));
    }
    return z;
}

// ================= fused encoder-hop kernel (unchanged from R14) =================
#define FLDH 136
#define FTILE (128 * FLDH)
#define SLD 20
#define F_STAGE_OFF (3 * FTILE * 2)
#define F_SMEM (F_STAGE_OFF + 8 * 16 * SLD * 4)

__global__ __launch_bounds__(TBS, 2)
void enc_fused_k(const float* __restrict__ gin,
                 const float* __restrict__ W_enc, const float* __restrict__ b_enc,
                 const float* __restrict__ W_mu, const float* __restrict__ b_mu,
                 const float* __restrict__ W_std, const float* __restrict__ b_std,
                 const float* __restrict__ eps_i,
                 float* __restrict__ out_mu, float* __restrict__ out_std,
                 float* __restrict__ h, int M, int dl) {
    extern __shared__ char smraw[];
    __half* actA = (__half*)smraw;
    __half* actB = actA + FTILE;
    __half* Wsm  = actB + FTILE;
    float*  stage = (float*)(smraw + F_STAGE_OFF);

    const int tid = threadIdx.x;
    const int wid = tid >> 5;
    const int lid = tid & 31;
    const int mBase = blockIdx.x * 128;
    const int warpRow = wid & 3;
    const int warpCol = wid >> 2;
    float* wstage = stage + wid * 16 * SLD;

    {
        const int r = tid >> 1;
        const int c0 = (tid & 1) * 64;
        const int gr = mBase + r;
        __half* dst = actA + r * FLDH + c0;
        if (gr < M) {
            const float* srow = gin + (size_t)gr * dl + c0;
#pragma unroll
            for (int i = 0; i < 16; i++) {
                float4 v = *(const float4*)(srow + i * 4);
                ((half2*)(dst + i * 4))[0] = __floats2half2_rn(v.x, v.y);
                ((half2*)(dst + i * 4))[1] = __floats2half2_rn(v.z, v.w);
            }
        } else {
#pragma unroll
            for (int i = 0; i < 32; i++) ((half2*)dst)[i] = __floats2half2_rn(0.f, 0.f);
        }
    }

    __half* cur = actA;
    __half* nxt = actB;

    auto do_layer = [&](const float* Wg, const float* bg, int MODE, float* gout) {
        {
            const int r = tid >> 1;
            const int c0 = (tid & 1) * 64;
            const float* srow = Wg + (size_t)r * dl + c0;
            __half* dst = Wsm + r * FLDH + c0;
#pragma unroll
            for (int i = 0; i < 16; i++) {
                float4 v = *(const float4*)(srow + i * 4);
                ((half2*)(dst + i * 4))[0] = __floats2half2_rn(v.x, v.y);
                ((half2*)(dst + i * 4))[1] = __floats2half2_rn(v.z, v.w);
            }
        }
        __syncthreads();

        wmma::fragment<wmma::accumulator, 16, 16, 16, float> acc[2][4];
#pragma unroll
        for (int i = 0; i < 2; i++)
#pragma unroll
            for (int j = 0; j < 4; j++) wmma::fill_fragment(acc[i][j], 0.0f);

#pragma unroll
        for (int kk = 0; kk < 8; kk++) {
            wmma::fragment<wmma::matrix_a, 16, 16, 16, __half, wmma::row_major> af[2];
            wmma::fragment<wmma::matrix_b, 16, 16, 16, __half, wmma::row_major> bf[4];
#pragma unroll
            for (int i = 0; i < 2; i++)
                wmma::load_matrix_sync(af[i], cur + (warpRow * 32 + i * 16) * FLDH + kk * 16, FLDH);
#pragma unroll
            for (int j = 0; j < 4; j++)
                wmma::load_matrix_sync(bf[j], Wsm + (kk * 16) * FLDH + warpCol * 64 + j * 16, FLDH);
#pragma unroll
            for (int i = 0; i < 2; i++)
#pragma unroll
                for (int j = 0; j < 4; j++)
                    wmma::mma_sync(acc[i][j], af[i], bf[j], acc[i][j]);
        }

        const int er = lid >> 1;
        const int ec = (lid & 1) * 8;
#pragma unroll
        for (int i = 0; i < 2; i++) {
#pragma unroll
            for (int j = 0; j < 4; j++) {
                wmma::store_matrix_sync(wstage, acc[i][j], SLD, wmma::mem_row_major);
                __syncwarp();
                const int rw = warpRow * 32 + i * 16 + er;
                const int cw = warpCol * 64 + j * 16 + ec;
                const int gr = mBase + rw;
                float z[8];
#pragma unroll
                for (int u = 0; u < 8; u++)
                    z[u] = wstage[er * SLD + ec + u] + __ldg(bg + cw + u);
                if (MODE == 0) {
#pragma unroll
                    for (int u = 0; u < 8; u++) z[u] = 1.0f / (1.0f + __expf(-z[u]));
                    half2 p0 = __floats2half2_rn(z[0], z[1]);
                    half2 p1 = __floats2half2_rn(z[2], z[3]);
                    half2 p2 = __floats2half2_rn(z[4], z[5]);
                    half2 p3 = __floats2half2_rn(z[6], z[7]);
                    half2* d = (half2*)(nxt + rw * FLDH + cw);
                    d[0] = p0; d[1] = p1; d[2] = p2; d[3] = p3;
                } else {
                    if (MODE == 2) {
#pragma unroll
                        for (int u = 0; u < 8; u++) {
                            float t = z[u] - 5.0f;
                            z[u] = fmaxf(t, 0.0f) + log1pf(__expf(-fabsf(t)));
                        }
                    }
                    if (gr < M) {
                        float* d = gout + (size_t)gr * dl + cw;
                        *(float4*)(d + 0) = make_float4(z[0], z[1], z[2], z[3]);
                        *(float4*)(d + 4) = make_float4(z[4], z[5], z[6], z[7]);
                    }
                }
                __syncwarp();
            }
        }
        __syncthreads();
    };

    for (int l = 0; l < 5; l++) {
        do_layer(W_enc + (size_t)l * dl * dl, b_enc + (size_t)l * dl, 0, nullptr);
        __half* t = cur; cur = nxt; nxt = t;
    }
    do_layer(W_mu, b_mu, 1, out_mu);
    do_layer(W_std, b_std, 2, out_std);

    __threadfence_block();
    __syncthreads();
    {
        const int r = tid >> 1;
        const int c0 = (tid & 1) * 64;
        const int gr = mBase + r;
        if (gr < M) {
            const size_t base = (size_t)gr * dl + c0;
#pragma unroll
            for (int i = 0; i < 16; i++) {
                float4 m4 = *(const float4*)(out_mu + base + i * 4);
                float4 s4 = *(const float4*)(out_std + base + i * 4);
                float4 e4 = *(const float4*)(eps_i + base + i * 4);
                float4 r4;
                r4.x = fmaf(s4.x, e4.x, m4.x);
                r4.y = fmaf(s4.y, e4.y, m4.y);
                r4.z = fmaf(s4.z, e4.z, m4.z);
                r4.w = fmaf(s4.w, e4.w, m4.w);
                *(float4*)(h + base + i * 4) = r4;
            }
        }
    }
}

// ================= fused decoder kernel =================
// 128-row block resident in SMEM fp16: 128->256->128->64->32->16->10(sigmoid) -> yp fp32
#define DLDH 264
#define DEC_ACT_B (128 * DLDH * 2)                 // 67584 bytes per act buffer
#define DEC_W_OFF (2 * DEC_ACT_B)                  // 135168
#define DEC_W_B 69632                              // max: 256 rows x 136 x 2
#define DEC_STAGE_OFF (DEC_W_OFF + DEC_W_B)        // 204800
#define DEC_SMEM (DEC_STAGE_OFF + 8 * 16 * SLD * 4)  // 215040

__global__ __launch_bounds__(TBS, 1)
void dec_fused_k(const float* __restrict__ hin,
                 const float* __restrict__ W0, const float* __restrict__ W1,
                 const float* __restrict__ W2, const float* __restrict__ W3,
                 const float* __restrict__ W4, const float* __restrict__ Wo,
                 const float* __restrict__ b0, const float* __restrict__ b1,
                 const float* __restrict__ b2, const float* __restrict__ b3,
                 const float* __restrict__ b4, const float* __restrict__ bo,
                 float* __restrict__ yp, int M,
                 int d1, int d2, int d3, int d4, int d5, int dout) {
    extern __shared__ char smraw[];
    __half* actA = (__half*)smraw;
    __half* actB = (__half*)(smraw + DEC_ACT_B);
    __half* Wsm  = (__half*)(smraw + DEC_W_OFF);
    float*  stage = (float*)(smraw + DEC_STAGE_OFF);

    const int tid = threadIdx.x;
    const int wid = tid >> 5;
    const int lid = tid & 31;
    const int mBase = blockIdx.x * 128;
    float* wstage = stage + wid * 16 * SLD;

    // ---- load input h block (fp32[128] -> fp16) ----
    {
        const int r = tid >> 1;
        const int c0 = (tid & 1) * 64;
        const int gr = mBase + r;
        __half* dst = actA + r * DLDH + c0;
        if (gr < M) {
            const float* srow = hin + (size_t)gr * 128 + c0;
#pragma unroll
            for (int i = 0; i < 16; i++) {
                float4 v = *(const float4*)(srow + i * 4);
                ((half2*)(dst + i * 4))[0] = __floats2half2_rn(v.x, v.y);
                ((half2*)(dst + i * 4))[1] = __floats2half2_rn(v.z, v.w);
            }
        } else {
#pragma unroll
            for (int i = 0; i < 32; i++) ((half2*)dst)[i] = __floats2half2_rn(0.f, 0.f);
        }
    }

    const float* Wl[6] = {W0, W1, W2, W3, W4, Wo};
    const float* bl[6] = {b0, b1, b2, b3, b4, bo};
    int dims[7] = {128, d1, d2, d3, d4, d5, dout};

    __half* cur = actA;
    __half* nxt = actB;

    for (int l = 0; l < 6; l++) {
        const int Kin = dims[l];
        const int Nout = dims[l + 1];
        const bool fin = (l == 5);
        const int NoutP = fin ? ((Nout + 15) & ~15) : Nout;  // pad final to 16
        const int LDW = NoutP + 8;
        const float* Wg = Wl[l];
        const float* bg = bl[l];

        // ---- load weights [Kin x Nout] fp32 -> fp16 SMEM (zero-pad to NoutP) ----
        {
            const int tx = tid & 63;
            const int ty = tid >> 6;
            const int col = tx * 4;
            const bool vec = ((Nout & 3) == 0);
            if (col < NoutP) {
                for (int r = ty; r < Kin; r += 4) {
                    __half* dst = Wsm + r * LDW + col;
                    if (vec && (col + 3 < Nout)) {
                        float4 v = *(const float4*)(Wg + (size_t)r * Nout + col);
                        ((half2*)dst)[0] = __floats2half2_rn(v.x, v.y);
                        ((half2*)dst)[1] = __floats2half2_rn(v.z, v.w);
                    } else {
                        float vv[4];
#pragma unroll
                        for (int u = 0; u < 4; u++)
                            vv[u] = (col + u < Nout) ? Wg[(size_t)r * Nout + col + u] : 0.0f;
                        ((half2*)dst)[0] = __floats2half2_rn(vv[0], vv[1]);
                        ((half2*)dst)[1] = __floats2half2_rn(vv[2], vv[3]);
                    }
                }
            }
        }
        __syncthreads();

        const int nct = NoutP >> 4;
        const int ks = Kin >> 4;
        for (int t = wid; t < 8 * nct; t += 8) {
            const int rt = t & 7;
            const int ct = t >> 3;
            wmma::fragment<wmma::accumulator, 16, 16, 16, float> acc;
            wmma::fill_fragment(acc, 0.0f);
            for (int kk = 0; kk < ks; kk++) {
                wmma::fragment<wmma::matrix_a, 16, 16, 16, __half, wmma::row_major> af;
                wmma::fragment<wmma::matrix_b, 16, 16, 16, __half, wmma::row_major> bf;
                wmma::load_matrix_sync(af, cur + (rt * 16) * DLDH + kk * 16, DLDH);
                wmma::load_matrix_sync(bf, Wsm + (kk * 16) * LDW + ct * 16, LDW);
                wmma::mma_sync(acc, af, bf, acc);
            }
            wmma::store_matrix_sync(wstage, acc, SLD, wmma::mem_row_major);
            __syncwarp();
            const int er = lid >> 1;
            const int ec = (lid & 1) * 8;
            const int rw = rt * 16 + er;
            const int cw = ct * 16 + ec;
            float z[8];
#pragma unroll
            for (int u = 0; u < 8; u++) {
                float b = (cw + u < Nout) ? __ldg(bg + cw + u) : 0.0f;
                z[u] = wstage[er * SLD + ec + u] + b;
            }
            if (!fin) {
#pragma unroll
                for (int u = 0; u < 8; u++) z[u] = fmaxf(z[u], 0.0f);  // relu
                half2* d = (half2*)(nxt + rw * DLDH + cw);
                d[0] = __floats2half2_rn(z[0], z[1]);
                d[1] = __floats2half2_rn(z[2], z[3]);
                d[2] = __floats2half2_rn(z[4], z[5]);
                d[3] = __floats2half2_rn(z[6], z[7]);
            } else {
#pragma unroll
                for (int u = 0; u < 8; u++) z[u] = 1.0f / (1.0f + __expf(-z[u]));  // sigmoid
                const int gr = mBase + rw;
                if (gr < M) {
                    float* d = yp + (size_t)gr * dout;
#pragma unroll
                    for (int u = 0; u < 8; u++)
                        if (cw + u < dout) d[cw + u] = z[u];
                }
            }
            __syncwarp();
        }
        __syncthreads();
        __half* tswap = cur; cur = nxt; nxt = tswap;
    }
}

// ---------------- WMMA fp16 GEMM (fp32 accumulate); OUTH=1 -> half output ----------------
#define BM 128
#define BN 128
#define BKH 64
#define LDAH 72
#define LDBH 136
#define LDCS 132
#define OFF_WS_H (128 * LDAH)
#define OFF_CS_B ((OFF_WS_H + BKH * LDBH) * 2)
#define SMEM_BYTES (OFF_CS_B + 128 * LDCS * 4)

template <int ACT, int OUTH>
__global__ __launch_bounds__(TBS, 2)
void wgemm_k(const float* __restrict__ A, const float* __restrict__ W,
             const float* __restrict__ bias, void* __restrict__ Cv,
             int M, int K, int Nout, int Ntrue, int ldC) {
    extern __shared__ char smraw[];
    __half* As = (__half*)smraw;
    __half* Ws = As + OFF_WS_H;
    float*  Cs = (float*)(smraw + OFF_CS_B);

    const int tid = threadIdx.x;
    const int wid = tid >> 5;
    const int mBase = blockIdx.x * BM;
    const int colBase = blockIdx.y * BN;
    const int warpRow = wid & 3;
    const int warpCol = wid >> 2;

    wmma::fragment<wmma::accumulator, 16, 16, 16, float> acc[2][4];
#pragma unroll
    for (int i = 0; i < 2; i++)
#pragma unroll
        for (int j = 0; j < 4; j++) wmma::fill_fragment(acc[i][j], 0.0f);

    const int ar  = tid >> 1;
    const int ac0 = (tid & 1) * 32;
    const int wr  = tid >> 2;
    const int wc0 = (tid & 3) * 32;
    const bool wVec = ((Nout & 3) == 0);
    const bool aVec = ((K & 3) == 0);

    const int nch = (K + BKH - 1) / BKH;
    for (int ch = 0; ch < nch; ch++) {
        const int k0 = ch * BKH;
        const int kc = min(BKH, K - k0);
        {
            const int gr = mBase + ar;
            const bool rok = (gr < M);
            const float* Arow = A + (size_t)gr * K + k0;
            __half* dst = As + ar * LDAH + ac0;
#pragma unroll
            for (int i = 0; i < 8; i++) {
                int c = ac0 + i * 4;
                float4 v = make_float4(0.f, 0.f, 0.f, 0.f);
                if (rok && aVec && (c + 3 < kc)) v = *(const float4*)(Arow + c);
                else if (rok) {
                    if (c + 0 < kc) v.x = Arow[c + 0];
                    if (c + 1 < kc) v.y = Arow[c + 1];
                    if (c + 2 < kc) v.z = Arow[c + 2];
                    if (c + 3 < kc) v.w = Arow[c + 3];
                }
                ((half2*)(dst + i * 4))[0] = __floats2half2_rn(v.x, v.y);
                ((half2*)(dst + i * 4))[1] = __floats2half2_rn(v.z, v.w);
            }
        }
        {
            const int kr = k0 + wr;
            const bool kok = (kr < K);
            const float* Wrow = W + (size_t)kr * Nout + colBase;
            __half* dst = Ws + wr * LDBH + wc0;
#pragma unroll
            for (int i = 0; i < 8; i++) {
                int c = wc0 + i * 4;
                int gc = colBase + c;
                float4 v = make_float4(0.f, 0.f, 0.f, 0.f);
                if (kok && wVec && (gc + 3 < Nout)) v = *(const float4*)(Wrow + c);
                else if (kok) {
                    if (gc + 0 < Nout) v.x = Wrow[c + 0];
                    if (gc + 1 < Nout) v.y = Wrow[c + 1];
                    if (gc + 2 < Nout) v.z = Wrow[c + 2];
                    if (gc + 3 < Nout) v.w = Wrow[c + 3];
                }
                ((half2*)(dst + i * 4))[0] = __floats2half2_rn(v.x, v.y);
                ((half2*)(dst + i * 4))[1] = __floats2half2_rn(v.z, v.w);
            }
        }
        __syncthreads();

        const int ks = (kc + 15) >> 4;
        for (int kk = 0; kk < ks; kk++) {
            wmma::fragment<wmma::matrix_a, 16, 16, 16, __half, wmma::row_major> af[2];
            wmma::fragment<wmma::matrix_b, 16, 16, 16, __half, wmma::row_major> bf[4];
#pragma unroll
            for (int i = 0; i < 2; i++)
                wmma::load_matrix_sync(af[i], As + (warpRow * 32 + i * 16) * LDAH + kk * 16, LDAH);
#pragma unroll
            for (int j = 0; j < 4; j++)
                wmma::load_matrix_sync(bf[j], Ws + (kk * 16) * LDBH + warpCol * 64 + j * 16, LDBH);
#pragma unroll
            for (int i = 0; i < 2; i++)
#pragma unroll
                for (int j = 0; j < 4; j++)
                    wmma::mma_sync(acc[i][j], af[i], bf[j], acc[i][j]);
        }
        __syncthreads();
    }

#pragma unroll
    for (int i = 0; i < 2; i++)
#pragma unroll
        for (int j = 0; j < 4; j++)
            wmma::store_matrix_sync(Cs + (warpRow * 32 + i * 16) * LDCS + warpCol * 64 + j * 16,
                                    acc[i][j], LDCS, wmma::mem_row_major);
    __syncthreads();

    {
        const int r = tid >> 1;
        const int ch2 = (tid & 1) * 64;
        const int gr = mBase + r;
        if (gr < M) {
            const float* Srow = Cs + r * LDCS + ch2;
            if (OUTH) {
                __half* Crow = (__half*)Cv + (size_t)gr * ldC + colBase + ch2;
#pragma unroll
                for (int c = 0; c < 64; c += 2) {
                    float z0 = Srow[c + 0];
                    float z1 = Srow[c + 1];
                    *(half2*)(Crow + c) = __floats2half2_rn(z0, z1);
                }
            } else {
                const int colRem = Ntrue - colBase - ch2;
                float* Crow = (float*)Cv + (size_t)gr * ldC + colBase + ch2;
                if (colRem >= 64 && ((ldC & 3) == 0)) {
#pragma unroll
                    for (int c = 0; c < 64; c += 4) {
                        float4 v;
                        v.x = apply_act(Srow[c + 0] + (bias ? __ldg(bias + colBase + ch2 + c + 0) : 0.f), ACT);
                        v.y = apply_act(Srow[c + 1] + (bias ? __ldg(bias + colBase + ch2 + c + 1) : 0.f), ACT);
                        v.z = apply_act(Srow[c + 2] + (bias ? __ldg(bias + colBase + ch2 + c + 2) : 0.f), ACT);
                        v.w = apply_act(Srow[c + 3] + (bias ? __ldg(bias + colBase + ch2 + c + 3) : 0.f), ACT);
                        *(float4*)(Crow + c) = v;
                    }
                } else {
                    for (int c = 0; c < 64 && c < colRem; c++) {
                        float z = Srow[c] + (bias ? __ldg(bias + colBase + ch2 + c) : 0.f);
                        Crow[c] = apply_act(z, ACT);
                    }
                }
            }
        }
    }
}

// ---------------- graph/CSR kernels ----------------
__global__ void count_deg_k(const int* __restrict__ dst, int E, int* __restrict__ counts) {
    int e = blockIdx.x * blockDim.x + threadIdx.x;
    if (e < E) atomicAdd(&counts[dst[e]], 1);
}

__global__ void scan_k(const int* __restrict__ counts, int* __restrict__ rowptr,
                       int* __restrict__ cursor, int n) {
    __shared__ int sm[1024];
    int tid = threadIdx.x;
    int chunk = (n + 1023) >> 10;
    int s = tid * chunk;
    int e = min(s + chunk, n);
    int sum = 0;
    for (int i = s; i < e && i < n; i++) sum += counts[i];
    sm[tid] = sum;
    __syncthreads();
    for (int off = 1; off < 1024; off <<= 1) {
        int v = (tid >= off) ? sm[tid - off] : 0;
        __syncthreads();
        sm[tid] += v;
        __syncthreads();
    }
    int run = (tid > 0) ? sm[tid - 1] : 0;
    for (int i = s; i < e && i < n; i++) {
        rowptr[i] = run;
        cursor[i] = run;
        run += counts[i];
    }
    if (e >= n) rowptr[n] = run;
}

__global__ void dinv_k(const int* __restrict__ counts, float* __restrict__ dinv, int n) {
    int i = blockIdx.x * blockDim.x + threadIdx.x;
    if (i < n) dinv[i] = rsqrtf((float)counts[i] + 1.0f);
}

__global__ void fill_csr_k(const int* __restrict__ src, const int* __restrict__ dst, int E,
                           int* __restrict__ cursor, int* __restrict__ csrc) {
    int e = blockIdx.x * blockDim.x + threadIdx.x;
    if (e < E) {
        int d = dst[e];
        int p = atomicAdd(&cursor[d], 1);
        csrc[p] = src[e];
    }
}

// gather-aggregate over fp16 g: 2 nodes per block, 64 threads each, half2 per thread
__global__ void agg_h_k(const __half* __restrict__ gh, float* __restrict__ out,
                        const int* __restrict__ rowptr, const int* __restrict__ csrc,
                        const float* __restrict__ dinv, const float* __restrict__ bias, int n) {
    const int node = blockIdx.x * 2 + (threadIdx.x >> 6);
    if (node >= n) return;
    const int j = threadIdx.x & 63;
    const float dn = dinv[node];
    half2 sv = ((const half2*)(gh + (size_t)node * 128))[j];
    float2 sf = __half22float2(sv);
    float a0 = sf.x * dn * dn + __ldg(bias + 2 * j);
    float a1 = sf.y * dn * dn + __ldg(bias + 2 * j + 1);
    const int beg = rowptr[node];
    const int end = rowptr[node + 1];
    for (int e = beg; e < end; e++) {
        const int s = csrc[e];
        const float w = dinv[s] * dn;
        half2 v = ((const half2*)(gh + (size_t)s * 128))[j];
        float2 f = __half22float2(v);
        a0 = fmaf(f.x, w, a0);
        a1 = fmaf(f.y, w, a1);
    }
    *(float2*)(out + (size_t)node * 128 + 2 * j) = make_float2(a0, a1);
}

__global__ void pool_k(const float* __restrict__ yp, const int* __restrict__ bids,
                       float* __restrict__ out, int N, int dout) {
    int g = blockIdx.x;
    int lo = 0, hi = N;
    while (lo < hi) { int m = (lo + hi) >> 1; if (bids[m] < g) lo = m + 1; else hi = m; }
    int start = lo;
    lo = start; hi = N;
    while (lo < hi) { int m = (lo + hi) >> 1; if (bids[m] < g + 1) lo = m + 1; else hi = m; }
    int end = lo;

    __shared__ float sm[16];
    if (threadIdx.x < dout) sm[threadIdx.x] = 0.0f;
    __syncthreads();
    float loc[10];
#pragma unroll
    for (int f = 0; f < 10; f++) loc[f] = 0.0f;
    for (int nidx = start + threadIdx.x; nidx < end; nidx += blockDim.x) {
#pragma unroll
        for (int f = 0; f < 10; f++) loc[f] += yp[(size_t)nidx * dout + f];
    }
#pragma unroll
    for (int f = 0; f < 10; f++) atomicAdd(&sm[f], loc[f]);
    __syncthreads();
    int cnt = end - start;
    float inv = 1.0f / (float)max(cnt, 1);
    if (threadIdx.x < dout) out[(size_t)g * dout + threadIdx.x] = sm[threadIdx.x] * inv;
}

// ---------------- launch ----------------
extern "C" void kernel_launch(void* const* d_in, const int* in_sizes, int n_in,
                              void* d_out, int out_size) {
    const float* x     = (const float*)d_in[0];
    const int*   ei    = (const int*)d_in[1];
    const int*   bids  = (const int*)d_in[2];
    const float* y     = (const float*)d_in[3];
    const float* eps   = (const float*)d_in[4];
    const float* W_in  = (const float*)d_in[5];
    const float* b_in  = (const float*)d_in[6];
    const float* W_gcn = (const float*)d_in[7];
    const float* b_gcn = (const float*)d_in[8];
    const float* W_enc = (const float*)d_in[9];
    const float* b_enc = (const float*)d_in[10];
    const float* W_mu  = (const float*)d_in[11];
    const float* b_mu  = (const float*)d_in[12];
    const float* W_std = (const float*)d_in[13];
    const float* b_std = (const float*)d_in[14];
    const float* Wd[5];
    const float* bd[5];
    for (int i = 0; i < 5; i++) {
        Wd[i] = (const float*)d_in[15 + 2 * i];
        bd[i] = (const float*)d_in[16 + 2 * i];
    }
    const float* Wo = (const float*)d_in[25];
    const float* bo = (const float*)d_in[26];

    const int dl    = in_sizes[6];             // 128
    const int din   = in_sizes[5] / dl;        // 32
    const int N     = in_sizes[0] / din;       // 50000
    const int E     = in_sizes[1] / 2;         // 800000
    const int dout  = in_sizes[26];            // 10
    const int G     = in_sizes[3] / dout;      // 256
    const int Khops = in_sizes[4] / (N * dl);  // 3

    float *h, *bufA, *bufB, *dinv;
    int *counts, *rowptr, *cursor, *csrc;
    cudaGetSymbolAddress((void**)&h, g_h);
    cudaGetSymbolAddress((void**)&bufA, g_bufA);
    cudaGetSymbolAddress((void**)&bufB, g_bufB);
    cudaGetSymbolAddress((void**)&dinv, g_dinv);
    cudaGetSymbolAddress((void**)&counts, g_counts);
    cudaGetSymbolAddress((void**)&rowptr, g_rowptr);
    cudaGetSymbolAddress((void**)&cursor, g_cursor);
    cudaGetSymbolAddress((void**)&csrc, g_csrc);

    __half* gh = (__half*)bufA;  // fp16 gcn output [N,128]

    float* out     = (float*)d_out;
    float* out_mu  = out + (size_t)G * dout;
    float* out_std = out_mu + (size_t)N * dl;
    float* out_y   = out_std + (size_t)N * dl;

    const int* src = ei;
    const int* dst = ei + E;

    cudaFuncSetAttribute((const void*)wgemm_k<1, 0>, cudaFuncAttributeMaxDynamicSharedMemorySize, SMEM_BYTES);
    cudaFuncSetAttribute((const void*)wgemm_k<0, 1>, cudaFuncAttributeMaxDynamicSharedMemorySize, SMEM_BYTES);
    cudaFuncSetAttribute(enc_fused_k, cudaFuncAttributeMaxDynamicSharedMemorySize, F_SMEM);
    cudaFuncSetAttribute(dec_fused_k, cudaFuncAttributeMaxDynamicSharedMemorySize, DEC_SMEM);

    // --- CSR + normalization ---
    cudaMemsetAsync(counts, 0, (size_t)N * sizeof(int));
    count_deg_k<<<(E + 255) / 256, 256>>>(dst, E, counts);
    scan_k<<<1, 1024>>>(counts, rowptr, cursor, N);
    dinv_k<<<(N + 255) / 256, 256>>>(counts, dinv, N);
    fill_csr_k<<<(E + 255) / 256, 256>>>(src, dst, E, cursor, csrc);

    const int gx = (N + 127) / 128;

    // --- input layer: h = sigmoid(x @ W_in + b_in) ---
    wgemm_k<1, 0><<<dim3(gx, 1), TBS, SMEM_BYTES>>>(x, W_in, b_in, h, N, din, dl, dl, dl);

    // --- K hops: gcn GEMM (fp16 out) -> fp16 gather-agg -> fused encoder chain ---
    for (int i = 0; i < Khops; i++) {
        wgemm_k<0, 1><<<dim3(gx, 1), TBS, SMEM_BYTES>>>(h, W_gcn, (const float*)nullptr,
                                                        gh, N, dl, dl, dl, dl);
        agg_h_k<<<(N + 1) / 2, 128>>>(gh, bufB, rowptr, csrc, dinv, b_gcn, N);
        enc_fused_k<<<gx, TBS, F_SMEM>>>(bufB, W_enc, b_enc, W_mu, b_mu, W_std, b_std,
                                         eps + (size_t)i * N * dl, out_mu, out_std, h, N, dl);
    }

    // --- fused decoder MLP -> yp [N, dout] in bufB ---
    int dd[6] = {dl, in_sizes[16], in_sizes[18], in_sizes[20], in_sizes[22], in_sizes[24]};
    dec_fused_k<<<gx, TBS, DEC_SMEM>>>(h, Wd[0], Wd[1], Wd[2], Wd[3], Wd[4], Wo,
                                       bd[0], bd[1], bd[2], bd[3], bd[4], bo,
                                       bufB, N, dd[1], dd[2], dd[3], dd[4], dd[5], dout);

    // --- pooling + y passthrough ---
    pool_k<<<G, 256>>>(bufB, bids, out, N, dout);
    cudaMemcpyAsync(out_y, y, (size_t)G * dout * sizeof(float), cudaMemcpyDeviceToDevice);
}

// round 17
// speedup vs baseline: 2.0956x; 1.0308x over previous
#include <cuda_runtime.h>
#include <cstdint>
#include <math.h>
#include <mma.h>
#include <cuda_fp16.h>

using namespace nvcuda;

#define TBS 256
static const int N_MAX = 50000;
static const int E_MAX = 800000;

// ---------------- static device scratch ----------------
__device__ float g_bufA[(size_t)N_MAX * 256];
__device__ float g_bufB[(size_t)N_MAX * 256];
__device__ int   g_counts[N_MAX];
__device__ int   g_rowptr[N_MAX + 1];
__device__ int   g_cursor[N_MAX];
__device__ int   g_csrc  [E_MAX];
__device__ float g_dinv  [N_MAX];

// =====================================================================
// k_hop: fused [agg gather] -> 5x sigmoid -> mu -> std -> reparam -> gcn
// SMEM: actA[34816] actB[34816] Wsm[34816] stage[10240] = 114688
// =====================================================================
#define FLDH 136
#define ACT_B 34816
#define SLD 20
#define HOP_STAGE_OFF (3 * ACT_B)
#define HOP_SMEM (HOP_STAGE_OFF + 8 * 16 * SLD * 4)

__global__ __launch_bounds__(TBS, 2)
void hop_k(const __half* __restrict__ ghin,      // [N,128] fp16 (prev g)
           const int* __restrict__ rowptr, const int* __restrict__ csrc,
           const float* __restrict__ dinv, const float* __restrict__ b_gcn,
           const float* __restrict__ W_enc, const float* __restrict__ b_enc,
           const float* __restrict__ W_mu, const float* __restrict__ b_mu,
           const float* __restrict__ W_std, const float* __restrict__ b_std,
           const float* __restrict__ W_gcn,
           const float* __restrict__ eps_i,
           __half* __restrict__ ghout,            // non-last: next g fp16
           float* __restrict__ out_mu, float* __restrict__ out_std,
           __half* __restrict__ hh,               // last: h fp16
           int M, int isLast) {
    extern __shared__ char smraw[];
    __half* actA = (__half*)smraw;
    __half* actB = (__half*)(smraw + ACT_B);
    __half* Wsm  = (__half*)(smraw + 2 * ACT_B);
    float*  stage = (float*)(smraw + HOP_STAGE_OFF);

    const int tid = threadIdx.x;
    const int wid = tid >> 5;
    const int lid = tid & 31;
    const int mBase = blockIdx.x * 128;
    const int warpRow = wid & 3;
    const int warpCol = wid >> 2;
    float* wstage = stage + wid * 16 * SLD;

    // ---- stage 0: aggregation gather into actA (fp16) ----
    // 4 threads/row, 16 half2 columns each, 2 row passes
    {
        const int q = tid & 3;
#pragma unroll
        for (int pass = 0; pass < 2; pass++) {
            const int r = (tid >> 2) + pass * 64;
            const int node = mBase + r;
            half2* dsm = (half2*)(actA + r * FLDH) + q * 16;
            if (node < M) {
                const float dn = dinv[node];
                float2 acc[16];
                const half2* grow = (const half2*)(ghin + (size_t)node * 128) + q * 16;
#pragma unroll
                for (int i = 0; i < 16; i++) {
                    float2 b = *(const float2*)(b_gcn + (q * 16 + i) * 2);
                    float2 s = __half22float2(grow[i]);
                    acc[i].x = fmaf(s.x, dn * dn, b.x);
                    acc[i].y = fmaf(s.y, dn * dn, b.y);
                }
                const int beg = rowptr[node];
                const int end = rowptr[node + 1];
                for (int e = beg; e < end; e++) {
                    const int sidx = csrc[e];
                    const float w = dinv[sidx] * dn;
                    const half2* srow = (const half2*)(ghin + (size_t)sidx * 128) + q * 16;
#pragma unroll
                    for (int i = 0; i < 16; i++) {
                        float2 f = __half22float2(srow[i]);
                        acc[i].x = fmaf(f.x, w, acc[i].x);
                        acc[i].y = fmaf(f.y, w, acc[i].y);
                    }
                }
#pragma unroll
                for (int i = 0; i < 16; i++) dsm[i] = __floats2half2_rn(acc[i].x, acc[i].y);
            } else {
#pragma unroll
                for (int i = 0; i < 16; i++) dsm[i] = __floats2half2_rn(0.f, 0.f);
            }
        }
    }
    __syncthreads();

    __half* cur = actA;
    __half* nxt = actB;

    // MODE: 0 sigmoid->nxt | 1 mu->nxt(+fp32 gmem if last) | 2 std/reparam | 3 gcn->ghout
    auto do_layer = [&](const float* Wg, const float* bg, int MODE) {
        {   // weights [128x128] fp32 -> fp16 SMEM
            const int r = tid >> 1;
            const int c0 = (tid & 1) * 64;
            const float* srow = Wg + (size_t)r * 128 + c0;
            __half* dst = Wsm + r * FLDH + c0;
#pragma unroll
            for (int i = 0; i < 16; i++) {
                float4 v = *(const float4*)(srow + i * 4);
                ((half2*)(dst + i * 4))[0] = __floats2half2_rn(v.x, v.y);
                ((half2*)(dst + i * 4))[1] = __floats2half2_rn(v.z, v.w);
            }
        }
        __syncthreads();

        wmma::fragment<wmma::accumulator, 16, 16, 16, float> acc[2][4];
#pragma unroll
        for (int i = 0; i < 2; i++)
#pragma unroll
            for (int j = 0; j < 4; j++) wmma::fill_fragment(acc[i][j], 0.0f);

#pragma unroll
        for (int kk = 0; kk < 8; kk++) {
            wmma::fragment<wmma::matrix_a, 16, 16, 16, __half, wmma::row_major> af[2];
            wmma::fragment<wmma::matrix_b, 16, 16, 16, __half, wmma::row_major> bf[4];
#pragma unroll
            for (int i = 0; i < 2; i++)
                wmma::load_matrix_sync(af[i], cur + (warpRow * 32 + i * 16) * FLDH + kk * 16, FLDH);
#pragma unroll
            for (int j = 0; j < 4; j++)
                wmma::load_matrix_sync(bf[j], Wsm + (kk * 16) * FLDH + warpCol * 64 + j * 16, FLDH);
#pragma unroll
            for (int i = 0; i < 2; i++)
#pragma unroll
                for (int j = 0; j < 4; j++)
                    wmma::mma_sync(acc[i][j], af[i], bf[j], acc[i][j]);
        }

        const int er = lid >> 1;
        const int ec = (lid & 1) * 8;
#pragma unroll
        for (int i = 0; i < 2; i++) {
#pragma unroll
            for (int j = 0; j < 4; j++) {
                wmma::store_matrix_sync(wstage, acc[i][j], SLD, wmma::mem_row_major);
                __syncwarp();
                const int rw = warpRow * 32 + i * 16 + er;
                const int cw = warpCol * 64 + j * 16 + ec;
                const int gr = mBase + rw;
                float z[8];
#pragma unroll
                for (int u = 0; u < 8; u++)
                    z[u] = wstage[er * SLD + ec + u] + (bg ? __ldg(bg + cw + u) : 0.0f);
                if (MODE == 0) {
#pragma unroll
                    for (int u = 0; u < 8; u++) z[u] = 1.0f / (1.0f + __expf(-z[u]));
                    half2* d = (half2*)(nxt + rw * FLDH + cw);
                    d[0] = __floats2half2_rn(z[0], z[1]);
                    d[1] = __floats2half2_rn(z[2], z[3]);
                    d[2] = __floats2half2_rn(z[4], z[5]);
                    d[3] = __floats2half2_rn(z[6], z[7]);
                } else if (MODE == 1) {
                    half2* d = (half2*)(nxt + rw * FLDH + cw);
                    d[0] = __floats2half2_rn(z[0], z[1]);
                    d[1] = __floats2half2_rn(z[2], z[3]);
                    d[2] = __floats2half2_rn(z[4], z[5]);
                    d[3] = __floats2half2_rn(z[6], z[7]);
                    if (isLast && gr < M) {
                        float* o = out_mu + (size_t)gr * 128 + cw;
                        *(float4*)(o + 0) = make_float4(z[0], z[1], z[2], z[3]);
                        *(float4*)(o + 4) = make_float4(z[4], z[5], z[6], z[7]);
                    }
                } else if (MODE == 2) {
                    // std = softplus(z - 5); h = mu + std*eps
                    float sp[8];
#pragma unroll
                    for (int u = 0; u < 8; u++) {
                        float t = z[u] - 5.0f;
                        sp[u] = fmaxf(t, 0.0f) + log1pf(__expf(-fabsf(t)));
                    }
                    float ev[8];
                    if (gr < M) {
                        const float* ep = eps_i + (size_t)gr * 128 + cw;
                        float4 e0 = *(const float4*)(ep + 0);
                        float4 e1 = *(const float4*)(ep + 4);
                        ev[0] = e0.x; ev[1] = e0.y; ev[2] = e0.z; ev[3] = e0.w;
                        ev[4] = e1.x; ev[5] = e1.y; ev[6] = e1.z; ev[7] = e1.w;
                    } else {
#pragma unroll
                        for (int u = 0; u < 8; u++) ev[u] = 0.0f;
                    }
                    half2* d = (half2*)(nxt + rw * FLDH + cw);
                    float hv[8];
#pragma unroll
                    for (int u = 0; u < 8; u += 2) {
                        float2 mu2 = __half22float2(d[u >> 1]);
                        hv[u]     = fmaf(sp[u], ev[u], mu2.x);
                        hv[u + 1] = fmaf(sp[u + 1], ev[u + 1], mu2.y);
                    }
                    d[0] = __floats2half2_rn(hv[0], hv[1]);
                    d[1] = __floats2half2_rn(hv[2], hv[3]);
                    d[2] = __floats2half2_rn(hv[4], hv[5]);
                    d[3] = __floats2half2_rn(hv[6], hv[7]);
                    if (isLast && gr < M) {
                        float* o = out_std + (size_t)gr * 128 + cw;
                        *(float4*)(o + 0) = make_float4(sp[0], sp[1], sp[2], sp[3]);
                        *(float4*)(o + 4) = make_float4(sp[4], sp[5], sp[6], sp[7]);
                        half2* hо = (half2*)(hh + (size_t)gr * 128 + cw);
                        hо[0] = __floats2half2_rn(hv[0], hv[1]);
                        hо[1] = __floats2half2_rn(hv[2], hv[3]);
                        hо[2] = __floats2half2_rn(hv[4], hv[5]);
                        hо[3] = __floats2half2_rn(hv[6], hv[7]);
                    }
                } else {  // MODE 3: gcn, no bias, no act -> ghout
                    if (gr < M) {
                        half2* d = (half2*)(ghout + (size_t)gr * 128 + cw);
                        d[0] = __floats2half2_rn(z[0], z[1]);
                        d[1] = __floats2half2_rn(z[2], z[3]);
                        d[2] = __floats2half2_rn(z[4], z[5]);
                        d[3] = __floats2half2_rn(z[6], z[7]);
                    }
                }
                __syncwarp();
            }
        }
        __syncthreads();
    };

    for (int l = 0; l < 5; l++) {
        do_layer(W_enc + (size_t)l * 128 * 128, b_enc + (size_t)l * 128, 0);
        __half* t = cur; cur = nxt; nxt = t;
    }
    do_layer(W_mu, b_mu, 1);    // mu -> nxt (no swap)
    do_layer(W_std, b_std, 2);  // h -> nxt
    { __half* t = cur; cur = nxt; nxt = t; }
    if (!isLast) do_layer(W_gcn, nullptr, 3);
}

// =====================================================================
// in_k: x -> sigmoid(x@W_in+b_in) -> @W_gcn -> gh (fp16)
// SMEM: actX[10240] actH[34816] Wsm[34816] stage[10240] = 90112
// =====================================================================
#define IN_ACTX_B 10240
#define IN_STAGE_OFF (IN_ACTX_B + 2 * ACT_B)
#define IN_SMEM (IN_STAGE_OFF + 8 * 16 * SLD * 4)

__global__ __launch_bounds__(TBS, 2)
void in_k(const float* __restrict__ x, const float* __restrict__ W_in,
          const float* __restrict__ b_in, const float* __restrict__ W_gcn,
          __half* __restrict__ gh, int M, int din) {
    extern __shared__ char smraw[];
    __half* actX = (__half*)smraw;                       // 128 x 40
    __half* actH = (__half*)(smraw + IN_ACTX_B);         // 128 x 136
    __half* Wsm  = (__half*)(smraw + IN_ACTX_B + ACT_B); // 128 x 136 max
    float*  stage = (float*)(smraw + IN_STAGE_OFF);

    const int tid = threadIdx.x;
    const int wid = tid >> 5;
    const int lid = tid & 31;
    const int mBase = blockIdx.x * 128;
    const int warpRow = wid & 3;
    const int warpCol = wid >> 2;
    float* wstage = stage + wid * 16 * SLD;
    const int LDX = 40;

    // load x block [128 x din(=32)] -> fp16
    {
        const int r = tid >> 1;
        const int c0 = (tid & 1) * 16;
        const int gr = mBase + r;
        __half* dst = actX + r * LDX + c0;
        if (gr < M && c0 < din) {
            const float* srow = x + (size_t)gr * din + c0;
#pragma unroll
            for (int i = 0; i < 4; i++) {
                float4 v = *(const float4*)(srow + i * 4);
                ((half2*)(dst + i * 4))[0] = __floats2half2_rn(v.x, v.y);
                ((half2*)(dst + i * 4))[1] = __floats2half2_rn(v.z, v.w);
            }
        } else {
#pragma unroll
            for (int i = 0; i < 8; i++) ((half2*)dst)[i] = __floats2half2_rn(0.f, 0.f);
        }
    }
    // load W_in [32 x 128] -> Wsm
    {
        const int r = tid >> 3;           // 0..31
        const int c0 = (tid & 7) * 16;
        const float* srow = W_in + (size_t)r * 128 + c0;
        __half* dst = Wsm + r * FLDH + c0;
#pragma unroll
        for (int i = 0; i < 4; i++) {
            float4 v = *(const float4*)(srow + i * 4);
            ((half2*)(dst + i * 4))[0] = __floats2half2_rn(v.x, v.y);
            ((half2*)(dst + i * 4))[1] = __floats2half2_rn(v.z, v.w);
        }
    }
    __syncthreads();

    // GEMM1: actX(128x32) @ W_in(32x128) + b_in, sigmoid -> actH
    {
        wmma::fragment<wmma::accumulator, 16, 16, 16, float> acc[2][4];
#pragma unroll
        for (int i = 0; i < 2; i++)
#pragma unroll
            for (int j = 0; j < 4; j++) wmma::fill_fragment(acc[i][j], 0.0f);
#pragma unroll
        for (int kk = 0; kk < 2; kk++) {
            wmma::fragment<wmma::matrix_a, 16, 16, 16, __half, wmma::row_major> af[2];
            wmma::fragment<wmma::matrix_b, 16, 16, 16, __half, wmma::row_major> bf[4];
#pragma unroll
            for (int i = 0; i < 2; i++)
                wmma::load_matrix_sync(af[i], actX + (warpRow * 32 + i * 16) * LDX + kk * 16, LDX);
#pragma unroll
            for (int j = 0; j < 4; j++)
                wmma::load_matrix_sync(bf[j], Wsm + (kk * 16) * FLDH + warpCol * 64 + j * 16, FLDH);
#pragma unroll
            for (int i = 0; i < 2; i++)
#pragma unroll
                for (int j = 0; j < 4; j++)
                    wmma::mma_sync(acc[i][j], af[i], bf[j], acc[i][j]);
        }
        const int er = lid >> 1;
        const int ec = (lid & 1) * 8;
#pragma unroll
        for (int i = 0; i < 2; i++) {
#pragma unroll
            for (int j = 0; j < 4; j++) {
                wmma::store_matrix_sync(wstage, acc[i][j], SLD, wmma::mem_row_major);
                __syncwarp();
                const int rw = warpRow * 32 + i * 16 + er;
                const int cw = warpCol * 64 + j * 16 + ec;
                float z[8];
#pragma unroll
                for (int u = 0; u < 8; u++) {
                    float v = wstage[er * SLD + ec + u] + __ldg(b_in + cw + u);
                    z[u] = 1.0f / (1.0f + __expf(-v));
                }
                half2* d = (half2*)(actH + rw * FLDH + cw);
                d[0] = __floats2half2_rn(z[0], z[1]);
                d[1] = __floats2half2_rn(z[2], z[3]);
                d[2] = __floats2half2_rn(z[4], z[5]);
                d[3] = __floats2half2_rn(z[6], z[7]);
                __syncwarp();
            }
        }
    }
    __syncthreads();

    // GEMM2: actH @ W_gcn -> gh (fp16, no bias/act)
    {
        const int r = tid >> 1;
        const int c0 = (tid & 1) * 64;
        const float* srow = W_gcn + (size_t)r * 128 + c0;
        __half* dst = Wsm + r * FLDH + c0;
#pragma unroll
        for (int i = 0; i < 16; i++) {
            float4 v = *(const float4*)(srow + i * 4);
            ((half2*)(dst + i * 4))[0] = __floats2half2_rn(v.x, v.y);
            ((half2*)(dst + i * 4))[1] = __floats2half2_rn(v.z, v.w);
        }
    }
    __syncthreads();
    {
        wmma::fragment<wmma::accumulator, 16, 16, 16, float> acc[2][4];
#pragma unroll
        for (int i = 0; i < 2; i++)
#pragma unroll
            for (int j = 0; j < 4; j++) wmma::fill_fragment(acc[i][j], 0.0f);
#pragma unroll
        for (int kk = 0; kk < 8; kk++) {
            wmma::fragment<wmma::matrix_a, 16, 16, 16, __half, wmma::row_major> af[2];
            wmma::fragment<wmma::matrix_b, 16, 16, 16, __half, wmma::row_major> bf[4];
#pragma unroll
            for (int i = 0; i < 2; i++)
                wmma::load_matrix_sync(af[i], actH + (warpRow * 32 + i * 16) * FLDH + kk * 16, FLDH);
#pragma unroll
            for (int j = 0; j < 4; j++)
                wmma::load_matrix_sync(bf[j], Wsm + (kk * 16) * FLDH + warpCol * 64 + j * 16, FLDH);
#pragma unroll
            for (int i = 0; i < 2; i++)
#pragma unroll
                for (int j = 0; j < 4; j++)
                    wmma::mma_sync(acc[i][j], af[i], bf[j], acc[i][j]);
        }
        const int er = lid >> 1;
        const int ec = (lid & 1) * 8;
#pragma unroll
        for (int i = 0; i < 2; i++) {
#pragma unroll
            for (int j = 0; j < 4; j++) {
                wmma::store_matrix_sync(wstage, acc[i][j], SLD, wmma::mem_row_major);
                __syncwarp();
                const int rw = warpRow * 32 + i * 16 + er;
                const int cw = warpCol * 64 + j * 16 + ec;
                const int gr = mBase + rw;
                if (gr < M) {
                    half2* d = (half2*)(gh + (size_t)gr * 128 + cw);
#pragma unroll
                    for (int u = 0; u < 4; u++)
                        d[u] = __floats2half2_rn(wstage[er * SLD + ec + 2 * u],
                                                 wstage[er * SLD + ec + 2 * u + 1]);
                }
                __syncwarp();
            }
        }
    }
}

// =====================================================================
// dec_k: fused decoder, 64-row blocks, occ 2
// SMEM: actA[33792] actB[33792] Wsm[34816] stage[10240] = 112640
// =====================================================================
#define DLD 264
#define DACT_B (64 * DLD * 2)
#define DEC_W_OFF (2 * DACT_B)
#define DEC_STAGE_OFF (DEC_W_OFF + 34816)
#define DEC_SMEM (DEC_STAGE_OFF + 8 * 16 * SLD * 4)

__global__ __launch_bounds__(TBS, 2)
void dec_k(const __half* __restrict__ hh,
           const float* __restrict__ W0, const float* __restrict__ W1,
           const float* __restrict__ W2, const float* __restrict__ W3,
           const float* __restrict__ W4, const float* __restrict__ Wo,
           const float* __restrict__ b0, const float* __restrict__ b1,
           const float* __restrict__ b2, const float* __restrict__ b3,
           const float* __restrict__ b4, const float* __restrict__ bo,
           float* __restrict__ yp, int M,
           int d1, int d2, int d3, int d4, int d5, int dout) {
    extern __shared__ char smraw[];
    __half* actA = (__half*)smraw;
    __half* actB = (__half*)(smraw + DACT_B);
    __half* Wsm  = (__half*)(smraw + DEC_W_OFF);
    float*  stage = (float*)(smraw + DEC_STAGE_OFF);

    const int tid = threadIdx.x;
    const int wid = tid >> 5;
    const int lid = tid & 31;
    const int mBase = blockIdx.x * 64;
    const int warpRow = wid & 3;      // 16-row group
    const int warpCol = wid >> 2;     // col frag parity
    float* wstage = stage + wid * 16 * SLD;

    // load hh block [64 x 128] fp16 -> actA
    {
        const int r = tid >> 2;
        const int c0 = (tid & 3) * 32;
        const int gr = mBase + r;
        half2* dst = (half2*)(actA + r * DLD + c0);
        if (gr < M) {
            const half2* srow = (const half2*)(hh + (size_t)gr * 128 + c0);
#pragma unroll
            for (int i = 0; i < 16; i++) dst[i] = srow[i];
        } else {
#pragma unroll
            for (int i = 0; i < 16; i++) dst[i] = __floats2half2_rn(0.f, 0.f);
        }
    }
    __syncthreads();

    const float* Wl[6] = {W0, W1, W2, W3, W4, Wo};
    const float* bl[6] = {b0, b1, b2, b3, b4, bo};
    int dims[7] = {128, d1, d2, d3, d4, d5, dout};

    __half* cur = actA;
    __half* nxt = actB;

    for (int l = 0; l < 6; l++) {
        const int Kin = dims[l];
        const int Nout = dims[l + 1];
        const bool fin = (l == 5);
        const int NoutP = (Nout + 15) & ~15;
        const float* Wg = Wl[l];
        const float* bg = bl[l];

        for (int nc0 = 0; nc0 < NoutP; nc0 += 128) {
            const int cwc = min(128, NoutP - nc0);
            const int nct = cwc >> 4;
            const int LDW = cwc + 8;

            wmma::fragment<wmma::accumulator, 16, 16, 16, float> acc[4];
#pragma unroll
            for (int a = 0; a < 4; a++) wmma::fill_fragment(acc[a], 0.0f);

            for (int kc0 = 0; kc0 < Kin; kc0 += 128) {
                const int kcc = min(128, Kin - kc0);
                // load W chunk [kcc x cwc] (cols nc0..) -> Wsm
                {
                    const int tx = tid & 31;
                    const int col = tx * 4;
                    const bool vec = ((Nout & 3) == 0);
                    if (col < cwc) {
                        for (int r = tid >> 5; r < kcc; r += 8) {
                            const int grow = kc0 + r;
                            __half* dst = Wsm + r * LDW + col;
                            const int gc = nc0 + col;
                            if (vec && (gc + 3 < Nout)) {
                                float4 v = *(const float4*)(Wg + (size_t)grow * Nout + gc);
                                ((half2*)dst)[0] = __floats2half2_rn(v.x, v.y);
                                ((half2*)dst)[1] = __floats2half2_rn(v.z, v.w);
                            } else {
                                float vv[4];
#pragma unroll
                                for (int u = 0; u < 4; u++)
                                    vv[u] = (gc + u < Nout) ? Wg[(size_t)grow * Nout + gc + u] : 0.0f;
                                ((half2*)dst)[0] = __floats2half2_rn(vv[0], vv[1]);
                                ((half2*)dst)[1] = __floats2half2_rn(vv[2], vv[3]);
                            }
                        }
                    }
                }
                __syncthreads();

                const int ks = kcc >> 4;
                for (int kk = 0; kk < ks; kk++) {
                    wmma::fragment<wmma::matrix_a, 16, 16, 16, __half, wmma::row_major> af;
                    wmma::load_matrix_sync(af, cur + (warpRow * 16) * DLD + kc0 + kk * 16, DLD);
#pragma unroll
                    for (int a = 0; a < 4; a++) {
                        const int ct = warpCol + 2 * a;
                        if (ct < nct) {
                            wmma::fragment<wmma::matrix_b, 16, 16, 16, __half, wmma::row_major> bf;
                            wmma::load_matrix_sync(bf, Wsm + (kk * 16) * LDW + ct * 16, LDW);
                            wmma::mma_sync(acc[a], af, bf, acc[a]);
                        }
                    }
                }
                __syncthreads();
            }

            // epilogue
            const int er = lid >> 1;
            const int ec = (lid & 1) * 8;
#pragma unroll
            for (int a = 0; a < 4; a++) {
                const int ct = warpCol + 2 * a;
                if (ct < nct) {
                    wmma::store_matrix_sync(wstage, acc[a], SLD, wmma::mem_row_major);
                    __syncwarp();
                    const int rw = warpRow * 16 + er;
                    const int cw = nc0 + ct * 16 + ec;
                    const int gr = mBase + rw;
                    float z[8];
#pragma unroll
                    for (int u = 0; u < 8; u++) {
                        float b = (cw + u < Nout) ? __ldg(bg + cw + u) : 0.0f;
                        z[u] = wstage[er * SLD + ec + u] + b;
                    }
                    if (!fin) {
#pragma unroll
                        for (int u = 0; u < 8; u++) z[u] = fmaxf(z[u], 0.0f);
                        half2* d = (half2*)(nxt + rw * DLD + cw);
                        d[0] = __floats2half2_rn(z[0], z[1]);
                        d[1] = __floats2half2_rn(z[2], z[3]);
                        d[2] = __floats2half2_rn(z[4], z[5]);
                        d[3] = __floats2half2_rn(z[6], z[7]);
                    } else {
                        if (gr < M) {
                            float* d = yp + (size_t)gr * dout;
#pragma unroll
                            for (int u = 0; u < 8; u++) {
                                if (cw + u < dout)
                                    d[cw + u] = 1.0f / (1.0f + __expf(-z[u]));
                            }
                        }
                    }
                    __syncwarp();
                }
            }
        }
        __syncthreads();
        __half* t = cur; cur = nxt; nxt = t;
    }
}

// ---------------- graph/CSR kernels ----------------
__global__ void count_deg_k(const int* __restrict__ dst, int E, int* __restrict__ counts) {
    int e = blockIdx.x * blockDim.x + threadIdx.x;
    if (e < E) atomicAdd(&counts[dst[e]], 1);
}

__global__ void scan_k(const int* __restrict__ counts, int* __restrict__ rowptr,
                       int* __restrict__ cursor, int n) {
    __shared__ int sm[1024];
    int tid = threadIdx.x;
    int chunk = (n + 1023) >> 10;
    int s = tid * chunk;
    int e = min(s + chunk, n);
    int sum = 0;
    for (int i = s; i < e && i < n; i++) sum += counts[i];
    sm[tid] = sum;
    __syncthreads();
    for (int off = 1; off < 1024; off <<= 1) {
        int v = (tid >= off) ? sm[tid - off] : 0;
        __syncthreads();
        sm[tid] += v;
        __syncthreads();
    }
    int run = (tid > 0) ? sm[tid - 1] : 0;
    for (int i = s; i < e && i < n; i++) {
        rowptr[i] = run;
        cursor[i] = run;
        run += counts[i];
    }
    if (e >= n) rowptr[n] = run;
}

__global__ void dinv_k(const int* __restrict__ counts, float* __restrict__ dinv, int n) {
    int i = blockIdx.x * blockDim.x + threadIdx.x;
    if (i < n) dinv[i] = rsqrtf((float)counts[i] + 1.0f);
}

__global__ void fill_csr_k(const int* __restrict__ src, const int* __restrict__ dst, int E,
                           int* __restrict__ cursor, int* __restrict__ csrc) {
    int e = blockIdx.x * blockDim.x + threadIdx.x;
    if (e < E) {
        int d = dst[e];
        int p = atomicAdd(&cursor[d], 1);
        csrc[p] = src[e];
    }
}

__global__ void pool_k(const float* __restrict__ yp, const int* __restrict__ bids,
                       float* __restrict__ out, int N, int dout) {
    int g = blockIdx.x;
    int lo = 0, hi = N;
    while (lo < hi) { int m = (lo + hi) >> 1; if (bids[m] < g) lo = m + 1; else hi = m; }
    int start = lo;
    lo = start; hi = N;
    while (lo < hi) { int m = (lo + hi) >> 1; if (bids[m] < g + 1) lo = m + 1; else hi = m; }
    int end = lo;

    __shared__ float sm[16];
    if (threadIdx.x < dout) sm[threadIdx.x] = 0.0f;
    __syncthreads();
    float loc[10];
#pragma unroll
    for (int f = 0; f < 10; f++) loc[f] = 0.0f;
    for (int nidx = start + threadIdx.x; nidx < end; nidx += blockDim.x) {
#pragma unroll
        for (int f = 0; f < 10; f++) loc[f] += yp[(size_t)nidx * dout + f];
    }
#pragma unroll
    for (int f = 0; f < 10; f++) atomicAdd(&sm[f], loc[f]);
    __syncthreads();
    int cnt = end - start;
    float inv = 1.0f / (float)max(cnt, 1);
    if (threadIdx.x < dout) out[(size_t)g * dout + threadIdx.x] = sm[threadIdx.x] * inv;
}

// ---------------- launch ----------------
extern "C" void kernel_launch(void* const* d_in, const int* in_sizes, int n_in,
                              void* d_out, int out_size) {
    const float* x     = (const float*)d_in[0];
    const int*   ei    = (const int*)d_in[1];
    const int*   bids  = (const int*)d_in[2];
    const float* y     = (const float*)d_in[3];
    const float* eps   = (const float*)d_in[4];
    const float* W_in  = (const float*)d_in[5];
    const float* b_in  = (const float*)d_in[6];
    const float* W_gcn = (const float*)d_in[7];
    const float* b_gcn = (const float*)d_in[8];
    const float* W_enc = (const float*)d_in[9];
    const float* b_enc = (const float*)d_in[10];
    const float* W_mu  = (const float*)d_in[11];
    const float* b_mu  = (const float*)d_in[12];
    const float* W_std = (const float*)d_in[13];
    const float* b_std = (const float*)d_in[14];
    const float* Wd[5];
    const float* bd[5];
    for (int i = 0; i < 5; i++) {
        Wd[i] = (const float*)d_in[15 + 2 * i];
        bd[i] = (const float*)d_in[16 + 2 * i];
    }
    const float* Wo = (const float*)d_in[25];
    const float* bo = (const float*)d_in[26];

    const int dl    = in_sizes[6];             // 128
    const int din   = in_sizes[5] / dl;        // 32
    const int N     = in_sizes[0] / din;       // 50000
    const int E     = in_sizes[1] / 2;         // 800000
    const int dout  = in_sizes[26];            // 10
    const int G     = in_sizes[3] / dout;      // 256
    const int Khops = in_sizes[4] / (N * dl);  // 3

    float *bufA, *bufB, *dinv;
    int *counts, *rowptr, *cursor, *csrc;
    cudaGetSymbolAddress((void**)&bufA, g_bufA);
    cudaGetSymbolAddress((void**)&bufB, g_bufB);
    cudaGetSymbolAddress((void**)&dinv, g_dinv);
    cudaGetSymbolAddress((void**)&counts, g_counts);
    cudaGetSymbolAddress((void**)&rowptr, g_rowptr);
    cudaGetSymbolAddress((void**)&cursor, g_cursor);
    cudaGetSymbolAddress((void**)&csrc, g_csrc);

    // gmem layout inside bufA (floats): ghA [0, N*64) | ghB [N*64, N*128) | yp [N*128, ...)
    __half* ghbuf[2] = {(__half*)bufA, (__half*)(bufA + (size_t)N * 64)};
    float* yp = bufA + (size_t)N * 128;
    __half* hh = (__half*)bufB;

    float* out     = (float*)d_out;
    float* out_mu  = out + (size_t)G * dout;
    float* out_std = out_mu + (size_t)N * dl;
    float* out_y   = out_std + (size_t)N * dl;

    const int* src = ei;
    const int* dst = ei + E;

    cudaFuncSetAttribute(in_k,  cudaFuncAttributeMaxDynamicSharedMemorySize, IN_SMEM);
    cudaFuncSetAttribute(hop_k, cudaFuncAttributeMaxDynamicSharedMemorySize, HOP_SMEM);
    cudaFuncSetAttribute(dec_k, cudaFuncAttributeMaxDynamicSharedMemorySize, DEC_SMEM);

    // --- CSR + normalization ---
    cudaMemsetAsync(counts, 0, (size_t)N * sizeof(int));
    count_deg_k<<<(E + 255) / 256, 256>>>(dst, E, counts);
    scan_k<<<1, 1024>>>(counts, rowptr, cursor, N);
    dinv_k<<<(N + 255) / 256, 256>>>(counts, dinv, N);
    fill_csr_k<<<(E + 255) / 256, 256>>>(src, dst, E, cursor, csrc);

    const int gx = (N + 127) / 128;

    // --- input: x -> h0 -> g0 = h0 @ W_gcn -> ghA ---
    in_k<<<gx, TBS, IN_SMEM>>>(x, W_in, b_in, W_gcn, ghbuf[0], N, din);

    // --- K hops (fused agg + encoder + reparam + next gcn) ---
    for (int i = 0; i < Khops; i++) {
        const int isLast = (i == Khops - 1);
        hop_k<<<gx, TBS, HOP_SMEM>>>(ghbuf[i & 1], rowptr, csrc, dinv, b_gcn,
                                     W_enc, b_enc, W_mu, b_mu, W_std, b_std, W_gcn,
                                     eps + (size_t)i * N * dl,
                                     ghbuf[(i + 1) & 1], out_mu, out_std, hh,
                                     N, isLast);
    }

    // --- fused decoder -> yp ---
    int dd[6] = {dl, in_sizes[16], in_sizes[18], in_sizes[20], in_sizes[22], in_sizes[24]};
    const int gxd = (N + 63) / 64;
    dec_k<<<gxd, TBS, DEC_SMEM>>>(hh, Wd[0], Wd[1], Wd[2], Wd[3], Wd[4], Wo,
                                  bd[0], bd[1], bd[2], bd[3], bd[4], bo,
                                  yp, N, dd[1], dd[2], dd[3], dd[4], dd[5], dout);

    // --- pooling + y passthrough ---
    pool_k<<<G, 256>>>(yp, bids, out, N, dout);
    cudaMemcpyAsync(out_y, y, (size_t)G * dout * sizeof(float), cudaMemcpyDeviceToDevice);
}